// round 1
// baseline (speedup 1.0000x reference)
#include <cuda_runtime.h>
#include <cuda_bf16.h>
#include <math.h>

// Problem constants
#define B_   2
#define S_   2048
#define H_   2048
#define NH_  32
#define NKV_ 8
#define D_   64
#define QKVF ((NH_ + 2 * NKV_) * D_)   // 3072
#define GQA_ (NH_ / NKV_)              // 4

// ---------------------------------------------------------------------------
// Device scratch (allocation-free contract: __device__ globals)
// ---------------------------------------------------------------------------
__device__ float g_qkv[(size_t)B_ * S_ * QKVF];        // 50.3 MB
__device__ float g_q  [(size_t)B_ * NH_  * S_ * D_];   // 33.5 MB  [b][h][s][d]
__device__ float g_k  [(size_t)B_ * NKV_ * S_ * D_];   //  8.4 MB  [b][kh][s][d]
__device__ float g_v  [(size_t)B_ * NKV_ * S_ * D_];   //  8.4 MB
__device__ float g_ctx[(size_t)B_ * S_ * NH_ * D_];    // 33.5 MB  [b][s][h*D+d]

// ---------------------------------------------------------------------------
// SGEMM: C[M,N] = A[M,K] @ B[K,N], row-major, dims multiples of tile sizes.
// 128x128 block tile, BK=8, 256 threads, 8x8 per-thread register tile.
// ---------------------------------------------------------------------------
__global__ __launch_bounds__(256)
void sgemm128(const float* __restrict__ A, const float* __restrict__ Bm,
              float* __restrict__ C, int M, int N, int K) {
    constexpr int BM = 128, BN = 128, BK = 8, TM = 8, TN = 8;
    __shared__ float As[BK][BM];
    __shared__ float Bs[BK][BN];

    const int tid = threadIdx.x;
    const int tx  = tid % (BN / TN);   // 0..15
    const int ty  = tid / (BN / TN);   // 0..15

    const float* Ab = A + (size_t)blockIdx.y * BM * K;
    const float* Bb = Bm + blockIdx.x * BN;
    float*       Cb = C + (size_t)blockIdx.y * BM * N + blockIdx.x * BN;

    const int aRow = tid >> 1;          // 0..127
    const int aCol = (tid & 1) << 2;    // 0 or 4
    const int bRow = tid >> 5;          // 0..7
    const int bCol = (tid & 31) << 2;   // 0..124

    float acc[TM][TN];
#pragma unroll
    for (int i = 0; i < TM; i++)
#pragma unroll
        for (int j = 0; j < TN; j++) acc[i][j] = 0.f;

    for (int k0 = 0; k0 < K; k0 += BK) {
        float4 av = *reinterpret_cast<const float4*>(Ab + (size_t)aRow * K + k0 + aCol);
        As[aCol + 0][aRow] = av.x;
        As[aCol + 1][aRow] = av.y;
        As[aCol + 2][aRow] = av.z;
        As[aCol + 3][aRow] = av.w;
        *reinterpret_cast<float4*>(&Bs[bRow][bCol]) =
            *reinterpret_cast<const float4*>(Bb + (size_t)(k0 + bRow) * N + bCol);
        __syncthreads();

#pragma unroll
        for (int kk = 0; kk < BK; kk++) {
            float ra[TM], rb[TN];
#pragma unroll
            for (int i = 0; i < TM; i++) ra[i] = As[kk][ty * TM + i];
#pragma unroll
            for (int j = 0; j < TN; j++) rb[j] = Bs[kk][tx * TN + j];
#pragma unroll
            for (int i = 0; i < TM; i++)
#pragma unroll
                for (int j = 0; j < TN; j++)
                    acc[i][j] = fmaf(ra[i], rb[j], acc[i][j]);
        }
        __syncthreads();
    }

#pragma unroll
    for (int i = 0; i < TM; i++) {
        float* crow = Cb + (size_t)(ty * TM + i) * N + tx * TN;
#pragma unroll
        for (int j = 0; j < TN; j += 4) {
            float4 v = make_float4(acc[i][j], acc[i][j + 1], acc[i][j + 2], acc[i][j + 3]);
            *reinterpret_cast<float4*>(crow + j) = v;
        }
    }
}

// ---------------------------------------------------------------------------
// RoPE (NeoX) + scatter q,k from g_qkv into [b][h][s][d] layouts.
// One thread per (b,s,head,d<32) pair. Double-precision range reduction keeps
// cos/sin accurate even for pos*inv_freq up to ~2047, regardless of fast-math.
// ---------------------------------------------------------------------------
__global__ void rope_scatter_kernel(const int* __restrict__ positions) {
    const int total = B_ * S_ * (NH_ + NKV_) * (D_ / 2);
    int idx = blockIdx.x * blockDim.x + threadIdx.x;
    if (idx >= total) return;

    const int d = idx & 31;
    int t = idx >> 5;
    const int h = t % (NH_ + NKV_); t /= (NH_ + NKV_);
    const int s = t % S_;
    const int b = t / S_;

    const float pos = (float)positions[s];
    const float inv = powf(10000.0f, -(float)(2 * d) / (float)D_);
    const float freq = pos * inv;                 // same fp32 rounding as reference
    // accurate range reduction in double (cheap: no transcendental DP ops)
    const double dr = (double)freq;
    const double kq = floor(dr * 0.15915494309189534 + 0.5);
    const float  rr = (float)(dr - kq * 6.283185307179586477);
    float sn, cs;
    sincosf(rr, &sn, &cs);

    const float* base = g_qkv + (size_t)(b * S_ + s) * QKVF;
    float x0, x1;
    float* dst;
    if (h < NH_) {
        x0 = base[h * D_ + d];
        x1 = base[h * D_ + d + 32];
        dst = g_q + (((size_t)(b * NH_ + h)) * S_ + s) * D_;
    } else {
        const int hk = h - NH_;
        x0 = base[NH_ * D_ + hk * D_ + d];
        x1 = base[NH_ * D_ + hk * D_ + d + 32];
        dst = g_k + (((size_t)(b * NKV_ + hk)) * S_ + s) * D_;
    }
    dst[d]      = x0 * cs - x1 * sn;
    dst[d + 32] = x1 * cs + x0 * sn;
}

// V scatter (no RoPE), float4 copies.
__global__ void vcopy_kernel() {
    const int total = B_ * S_ * NKV_ * D_ / 4;
    int idx = blockIdx.x * blockDim.x + threadIdx.x;
    if (idx >= total) return;
    const int c4 = idx & (D_ / 4 - 1);
    int t = idx >> 4;
    const int h = t % NKV_; t /= NKV_;
    const int s = t % S_;
    const int b = t / S_;
    const float4 v = *reinterpret_cast<const float4*>(
        g_qkv + (size_t)(b * S_ + s) * QKVF + (NH_ + NKV_) * D_ + h * D_ + c4 * 4);
    *reinterpret_cast<float4*>(
        g_v + (((size_t)(b * NKV_ + h)) * S_ + s) * D_ + c4 * 4) = v;
}

// ---------------------------------------------------------------------------
// Causal flash attention (fp32, online softmax).
// Block: 128 threads, one (b, h, 64-row q tile). Iterates 64-row K/V tiles.
// Thread layout: ty=tid/8 (16 row groups x 4 rows), tx=tid%8 (8 col groups x 8).
// smem: Qs[64][65], KPs[64][65] (K tile, reused for P), Vs[64][65].
// ---------------------------------------------------------------------------
#define ATTN_SMEM (3 * 64 * 65 * 4)

__global__ __launch_bounds__(128)
void attn_kernel(const float* __restrict__ qg, const float* __restrict__ kg,
                 const float* __restrict__ vg, float* __restrict__ ctx) {
    extern __shared__ float sm[];
    float* Qs  = sm;
    float* KPs = sm + 64 * 65;
    float* Vs  = sm + 2 * 64 * 65;

    const int qtile = gridDim.x - 1 - blockIdx.x;  // heavy tiles launch first
    const int h = blockIdx.y;
    const int b = blockIdx.z;
    const int kvh = h / GQA_;

    const float* qbase = qg + (((size_t)(b * NH_ + h)) * S_ + qtile * 64) * D_;
    const float* kbase = kg + ((size_t)(b * NKV_ + kvh)) * S_ * D_;
    const float* vbase = vg + ((size_t)(b * NKV_ + kvh)) * S_ * D_;

    const int tid = threadIdx.x;
    const int tx = tid & 7;
    const int ty = tid >> 3;

    // Load Q tile (64 x 64)
    for (int i = tid; i < 64 * D_ / 4; i += 128) {
        const int r = i >> 4;
        const int c = (i & 15) << 2;
        float4 v4 = *reinterpret_cast<const float4*>(qbase + r * D_ + c);
        Qs[r * 65 + c]     = v4.x;
        Qs[r * 65 + c + 1] = v4.y;
        Qs[r * 65 + c + 2] = v4.z;
        Qs[r * 65 + c + 3] = v4.w;
    }

    float o[4][8];
    float m[4], l[4];
#pragma unroll
    for (int i = 0; i < 4; i++) {
        m[i] = -1e30f; l[i] = 0.f;
#pragma unroll
        for (int j = 0; j < 8; j++) o[i][j] = 0.f;
    }

    for (int kt = 0; kt <= qtile; kt++) {
        __syncthreads();  // prior P/V reads done (and Q stores visible on iter 0)
        for (int i = tid; i < 64 * D_ / 4; i += 128) {
            const int r = i >> 4;
            const int c = (i & 15) << 2;
            float4 k4 = *reinterpret_cast<const float4*>(kbase + (size_t)(kt * 64 + r) * D_ + c);
            KPs[r * 65 + c]     = k4.x;
            KPs[r * 65 + c + 1] = k4.y;
            KPs[r * 65 + c + 2] = k4.z;
            KPs[r * 65 + c + 3] = k4.w;
            float4 v4 = *reinterpret_cast<const float4*>(vbase + (size_t)(kt * 64 + r) * D_ + c);
            Vs[r * 65 + c]     = v4.x;
            Vs[r * 65 + c + 1] = v4.y;
            Vs[r * 65 + c + 2] = v4.z;
            Vs[r * 65 + c + 3] = v4.w;
        }
        __syncthreads();

        // S = Q @ K^T : each thread computes 4 rows x 8 cols
        float sc[4][8];
#pragma unroll
        for (int i = 0; i < 4; i++)
#pragma unroll
            for (int j = 0; j < 8; j++) sc[i][j] = 0.f;

#pragma unroll 8
        for (int d = 0; d < D_; d++) {
            float qa[4], kb[8];
#pragma unroll
            for (int i = 0; i < 4; i++) qa[i] = Qs[(ty * 4 + i) * 65 + d];
#pragma unroll
            for (int j = 0; j < 8; j++) kb[j] = KPs[(tx * 8 + j) * 65 + d];
#pragma unroll
            for (int i = 0; i < 4; i++)
#pragma unroll
                for (int j = 0; j < 8; j++)
                    sc[i][j] = fmaf(qa[i], kb[j], sc[i][j]);
        }

        // Mask + online softmax (row state replicated across the 8 col lanes)
        const bool diag = (kt == qtile);
#pragma unroll
        for (int i = 0; i < 4; i++) {
            const int qgl = qtile * 64 + ty * 4 + i;
            float rmax = -1e30f;
#pragma unroll
            for (int j = 0; j < 8; j++) {
                float sv = sc[i][j] * 0.125f;  // 1/sqrt(64)
                if (diag && (kt * 64 + tx * 8 + j) > qgl) sv = -1e30f;
                sc[i][j] = sv;
                rmax = fmaxf(rmax, sv);
            }
            rmax = fmaxf(rmax, __shfl_xor_sync(0xffffffffu, rmax, 1));
            rmax = fmaxf(rmax, __shfl_xor_sync(0xffffffffu, rmax, 2));
            rmax = fmaxf(rmax, __shfl_xor_sync(0xffffffffu, rmax, 4));
            const float mn = fmaxf(m[i], rmax);
            const float corr = expf(m[i] - mn);
            float rsum = 0.f;
#pragma unroll
            for (int j = 0; j < 8; j++) {
                const float p = expf(sc[i][j] - mn);
                sc[i][j] = p;
                rsum += p;
            }
            rsum += __shfl_xor_sync(0xffffffffu, rsum, 1);
            rsum += __shfl_xor_sync(0xffffffffu, rsum, 2);
            rsum += __shfl_xor_sync(0xffffffffu, rsum, 4);
            l[i] = l[i] * corr + rsum;
            m[i] = mn;
#pragma unroll
            for (int j = 0; j < 8; j++) o[i][j] *= corr;
        }

        __syncthreads();  // all K reads done before overwriting with P
#pragma unroll
        for (int i = 0; i < 4; i++)
#pragma unroll
            for (int j = 0; j < 8; j++)
                KPs[(ty * 4 + i) * 65 + tx * 8 + j] = sc[i][j];
        __syncthreads();  // P visible

        // O += P @ V : thread owns 4 rows x 8 output dims
#pragma unroll 4
        for (int jj = 0; jj < 64; jj++) {
            float pv[4], vb[8];
#pragma unroll
            for (int i = 0; i < 4; i++) pv[i] = KPs[(ty * 4 + i) * 65 + jj];
#pragma unroll
            for (int j = 0; j < 8; j++) vb[j] = Vs[jj * 65 + tx * 8 + j];
#pragma unroll
            for (int i = 0; i < 4; i++)
#pragma unroll
                for (int j = 0; j < 8; j++)
                    o[i][j] = fmaf(pv[i], vb[j], o[i][j]);
        }
    }

    // Normalize and write ctx [b][s][h*D+d]
#pragma unroll
    for (int i = 0; i < 4; i++) {
        const float invl = 1.0f / l[i];
        const int qgl = qtile * 64 + ty * 4 + i;
        float* dst = ctx + ((size_t)(b * S_ + qgl)) * (NH_ * D_) + h * D_ + tx * 8;
#pragma unroll
        for (int j = 0; j < 8; j++) dst[j] = o[i][j] * invl;
    }
}

// ---------------------------------------------------------------------------
// Launch
// ---------------------------------------------------------------------------
extern "C" void kernel_launch(void* const* d_in, const int* in_sizes, int n_in,
                              void* d_out, int out_size) {
    const int*   positions = (const int*)d_in[0];
    const float* hidden    = (const float*)d_in[1];
    const float* Wqkv      = (const float*)d_in[2];
    const float* Wo        = (const float*)d_in[3];
    float* out = (float*)d_out;

    float *qkv_p, *q_p, *k_p, *v_p, *ctx_p;
    cudaGetSymbolAddress((void**)&qkv_p, g_qkv);
    cudaGetSymbolAddress((void**)&q_p,   g_q);
    cudaGetSymbolAddress((void**)&k_p,   g_k);
    cudaGetSymbolAddress((void**)&v_p,   g_v);
    cudaGetSymbolAddress((void**)&ctx_p, g_ctx);

    // 1. QKV projection: [4096,2048] @ [2048,3072]
    sgemm128<<<dim3(QKVF / 128, (B_ * S_) / 128), 256>>>(
        hidden, Wqkv, qkv_p, B_ * S_, QKVF, H_);

    // 2. RoPE + scatter
    {
        const int total = B_ * S_ * (NH_ + NKV_) * (D_ / 2);
        rope_scatter_kernel<<<(total + 255) / 256, 256>>>(positions);
        const int vtotal = B_ * S_ * NKV_ * D_ / 4;
        vcopy_kernel<<<(vtotal + 255) / 256, 256>>>();
    }

    // 3. Causal GQA flash attention
    cudaFuncSetAttribute(attn_kernel, cudaFuncAttributeMaxDynamicSharedMemorySize, ATTN_SMEM);
    attn_kernel<<<dim3(S_ / 64, NH_, B_), 128, ATTN_SMEM>>>(q_p, k_p, v_p, ctx_p);

    // 4. Output projection: [4096,2048] @ [2048,2048]
    sgemm128<<<dim3(H_ / 128, (B_ * S_) / 128), 256>>>(
        ctx_p, Wo, out, B_ * S_, H_, NH_ * D_);
}

// round 2
// speedup vs baseline: 1.2055x; 1.2055x over previous
#include <cuda_runtime.h>
#include <cuda_bf16.h>
#include <math.h>
#include <stdint.h>

// Problem constants
#define B_   2
#define S_   2048
#define H_   2048
#define NH_  32
#define NKV_ 8
#define D_   64
#define QKVF ((NH_ + 2 * NKV_) * D_)   // 3072
#define GQA_ (NH_ / NKV_)              // 4

// ---------------------------------------------------------------------------
// Device scratch (allocation-free contract: __device__ globals)
// ---------------------------------------------------------------------------
__device__ float g_qkv[(size_t)B_ * S_ * QKVF];        // 50.3 MB
__device__ float g_q  [(size_t)B_ * NH_  * S_ * D_];   // 33.5 MB  [b][h][s][d]
__device__ float g_k  [(size_t)B_ * NKV_ * S_ * D_];   //  8.4 MB  [b][kh][s][d]
__device__ float g_v  [(size_t)B_ * NKV_ * S_ * D_];   //  8.4 MB
__device__ float g_ctx[(size_t)B_ * S_ * NH_ * D_];    // 33.5 MB  [b][s][h*D+d]

// ---------------------------------------------------------------------------
// Tensor-core GEMM: C[M,N] = A[M,K] @ B[K,N], row-major, fp32 in/out.
// mma.sync.m16n8k8.tf32 with 3xTF32 error compensation (fp32-level accuracy).
// 128x128x32 block tile, 256 threads (8 warps, 4x2), warp tile 32x64.
// cp.async double-buffered mainloop.
// ---------------------------------------------------------------------------
#define GBM 128
#define GBN 128
#define GBK 32
#define ASTR 36                    // A smem row stride (floats): conflict-free frags
#define BSTR 136                   // B smem row stride
#define A_TILE_F (GBM * ASTR)      // 4608 floats
#define B_TILE_F (GBK * BSTR)      // 4352 floats
#define GEMM_SMEM ((2 * (A_TILE_F + B_TILE_F)) * 4)   // 71680 bytes

__device__ __forceinline__ void cp_async16(float* s, const float* g) {
    uint32_t sa = (uint32_t)__cvta_generic_to_shared(s);
    asm volatile("cp.async.cg.shared.global [%0], [%1], 16;\n" :: "r"(sa), "l"(g));
}
__device__ __forceinline__ void cp_commit() {
    asm volatile("cp.async.commit_group;\n");
}
__device__ __forceinline__ void tf32_split(float x, uint32_t& hi, uint32_t& lo) {
    asm("cvt.rna.tf32.f32 %0, %1;" : "=r"(hi) : "f"(x));
    lo = __float_as_uint(x - __uint_as_float(hi));
}
__device__ __forceinline__ void mma_tf32(float* c, const uint32_t* a,
                                         uint32_t b0, uint32_t b1) {
    asm volatile(
        "mma.sync.aligned.m16n8k8.row.col.f32.tf32.tf32.f32 "
        "{%0,%1,%2,%3},{%4,%5,%6,%7},{%8,%9},{%0,%1,%2,%3};"
        : "+f"(c[0]), "+f"(c[1]), "+f"(c[2]), "+f"(c[3])
        : "r"(a[0]), "r"(a[1]), "r"(a[2]), "r"(a[3]), "r"(b0), "r"(b1));
}

__device__ __forceinline__ void gemm_load_tiles(
    float* As, float* Bs, const float* Ag, const float* Bg,
    int k0, int K, int N, int tid) {
#pragma unroll
    for (int i = 0; i < 4; i++) {                 // A: 128 x 32 (1024 float4)
        int idx = tid + i * 256;
        int r = idx >> 3, c = (idx & 7) << 2;
        cp_async16(&As[r * ASTR + c], Ag + (size_t)r * K + k0 + c);
    }
#pragma unroll
    for (int i = 0; i < 4; i++) {                 // B: 32 x 128 (1024 float4)
        int idx = tid + i * 256;
        int r = idx >> 5, c = (idx & 31) << 2;
        cp_async16(&Bs[r * BSTR + c], Bg + (size_t)(k0 + r) * N + c);
    }
}

__global__ __launch_bounds__(256)
void gemm_tf32x3(const float* __restrict__ A, const float* __restrict__ Bm,
                 float* __restrict__ C, int M, int N, int K) {
    extern __shared__ float sh[];
    float* As[2] = { sh, sh + A_TILE_F };
    float* Bs[2] = { sh + 2 * A_TILE_F, sh + 2 * A_TILE_F + B_TILE_F };

    const int tid  = threadIdx.x;
    const int wid  = tid >> 5;
    const int lane = tid & 31;
    const int wm = (wid & 3) * 32;     // warp m offset within block tile
    const int wn = (wid >> 2) * 64;    // warp n offset
    const int g  = lane >> 2;          // groupID (0..7)
    const int tg = lane & 3;           // thread-in-group (0..3)

    const float* Ag = A + (size_t)blockIdx.y * GBM * K;
    const float* Bg = Bm + blockIdx.x * GBN;

    float acc[2][8][4];
#pragma unroll
    for (int mi = 0; mi < 2; mi++)
#pragma unroll
        for (int ni = 0; ni < 8; ni++)
#pragma unroll
            for (int r = 0; r < 4; r++) acc[mi][ni][r] = 0.f;

    const int NIT = K / GBK;
    gemm_load_tiles(As[0], Bs[0], Ag, Bg, 0, K, N, tid);
    cp_commit();

    for (int it = 0; it < NIT; ++it) {
        const int cur = it & 1;
        if (it + 1 < NIT) {
            gemm_load_tiles(As[cur ^ 1], Bs[cur ^ 1], Ag, Bg, (it + 1) * GBK, K, N, tid);
            cp_commit();
            asm volatile("cp.async.wait_group 1;\n");
        } else {
            asm volatile("cp.async.wait_group 0;\n");
        }
        __syncthreads();

        const float* Ac = As[cur];
        const float* Bc = Bs[cur];
#pragma unroll
        for (int ks = 0; ks < 4; ks++) {
            const int k0 = ks * 8;
            uint32_t ah[2][4], al[2][4];
#pragma unroll
            for (int mi = 0; mi < 2; mi++) {
                const int mr = wm + mi * 16;
                float a0 = Ac[(mr + g)     * ASTR + k0 + tg];
                float a1 = Ac[(mr + g + 8) * ASTR + k0 + tg];
                float a2 = Ac[(mr + g)     * ASTR + k0 + tg + 4];
                float a3 = Ac[(mr + g + 8) * ASTR + k0 + tg + 4];
                tf32_split(a0, ah[mi][0], al[mi][0]);
                tf32_split(a1, ah[mi][1], al[mi][1]);
                tf32_split(a2, ah[mi][2], al[mi][2]);
                tf32_split(a3, ah[mi][3], al[mi][3]);
            }
#pragma unroll
            for (int ni = 0; ni < 8; ni++) {
                const int nc = wn + ni * 8 + g;
                float b0 = Bc[(k0 + tg)     * BSTR + nc];
                float b1 = Bc[(k0 + tg + 4) * BSTR + nc];
                uint32_t bh0, bl0, bh1, bl1;
                tf32_split(b0, bh0, bl0);
                tf32_split(b1, bh1, bl1);
#pragma unroll
                for (int mi = 0; mi < 2; mi++) {
                    mma_tf32(acc[mi][ni], ah[mi], bh0, bh1);   // hi*hi
                    mma_tf32(acc[mi][ni], al[mi], bh0, bh1);   // lo*hi
                    mma_tf32(acc[mi][ni], ah[mi], bl0, bl1);   // hi*lo
                }
            }
        }
        __syncthreads();
    }

    // Epilogue: each (mi,ni) fragment -> rows {r, r+8}, cols {c, c+1}
#pragma unroll
    for (int mi = 0; mi < 2; mi++) {
        const int row = blockIdx.y * GBM + wm + mi * 16 + g;
#pragma unroll
        for (int ni = 0; ni < 8; ni++) {
            const int col = blockIdx.x * GBN + wn + ni * 8 + 2 * tg;
            float2 v01 = make_float2(acc[mi][ni][0], acc[mi][ni][1]);
            float2 v23 = make_float2(acc[mi][ni][2], acc[mi][ni][3]);
            *reinterpret_cast<float2*>(C + (size_t)row * N + col) = v01;
            *reinterpret_cast<float2*>(C + (size_t)(row + 8) * N + col) = v23;
        }
    }
}

// ---------------------------------------------------------------------------
// RoPE (NeoX) + scatter q,k from g_qkv into [b][h][s][d] layouts.
// ---------------------------------------------------------------------------
__global__ void rope_scatter_kernel(const int* __restrict__ positions) {
    const int total = B_ * S_ * (NH_ + NKV_) * (D_ / 2);
    int idx = blockIdx.x * blockDim.x + threadIdx.x;
    if (idx >= total) return;

    const int d = idx & 31;
    int t = idx >> 5;
    const int h = t % (NH_ + NKV_); t /= (NH_ + NKV_);
    const int s = t % S_;
    const int b = t / S_;

    const float pos = (float)positions[s];
    const float inv = powf(10000.0f, -(float)(2 * d) / (float)D_);
    const float freq = pos * inv;
    const double dr = (double)freq;
    const double kq = floor(dr * 0.15915494309189534 + 0.5);
    const float  rr = (float)(dr - kq * 6.283185307179586477);
    float sn, cs;
    sincosf(rr, &sn, &cs);

    const float* base = g_qkv + (size_t)(b * S_ + s) * QKVF;
    float x0, x1;
    float* dst;
    if (h < NH_) {
        x0 = base[h * D_ + d];
        x1 = base[h * D_ + d + 32];
        dst = g_q + (((size_t)(b * NH_ + h)) * S_ + s) * D_;
    } else {
        const int hk = h - NH_;
        x0 = base[NH_ * D_ + hk * D_ + d];
        x1 = base[NH_ * D_ + hk * D_ + d + 32];
        dst = g_k + (((size_t)(b * NKV_ + hk)) * S_ + s) * D_;
    }
    dst[d]      = x0 * cs - x1 * sn;
    dst[d + 32] = x1 * cs + x0 * sn;
}

// V scatter (no RoPE), float4 copies.
__global__ void vcopy_kernel() {
    const int total = B_ * S_ * NKV_ * D_ / 4;
    int idx = blockIdx.x * blockDim.x + threadIdx.x;
    if (idx >= total) return;
    const int c4 = idx & (D_ / 4 - 1);
    int t = idx >> 4;
    const int h = t % NKV_; t /= NKV_;
    const int s = t % S_;
    const int b = t / S_;
    const float4 v = *reinterpret_cast<const float4*>(
        g_qkv + (size_t)(b * S_ + s) * QKVF + (NH_ + NKV_) * D_ + h * D_ + c4 * 4);
    *reinterpret_cast<float4*>(
        g_v + (((size_t)(b * NKV_ + h)) * S_ + s) * D_ + c4 * 4) = v;
}

// ---------------------------------------------------------------------------
// Causal flash attention (fp32, online softmax). Unchanged from R1.
// ---------------------------------------------------------------------------
#define ATTN_SMEM (3 * 64 * 65 * 4)

__global__ __launch_bounds__(128)
void attn_kernel(const float* __restrict__ qg, const float* __restrict__ kg,
                 const float* __restrict__ vg, float* __restrict__ ctx) {
    extern __shared__ float sm[];
    float* Qs  = sm;
    float* KPs = sm + 64 * 65;
    float* Vs  = sm + 2 * 64 * 65;

    const int qtile = gridDim.x - 1 - blockIdx.x;
    const int h = blockIdx.y;
    const int b = blockIdx.z;
    const int kvh = h / GQA_;

    const float* qbase = qg + (((size_t)(b * NH_ + h)) * S_ + qtile * 64) * D_;
    const float* kbase = kg + ((size_t)(b * NKV_ + kvh)) * S_ * D_;
    const float* vbase = vg + ((size_t)(b * NKV_ + kvh)) * S_ * D_;

    const int tid = threadIdx.x;
    const int tx = tid & 7;
    const int ty = tid >> 3;

    for (int i = tid; i < 64 * D_ / 4; i += 128) {
        const int r = i >> 4;
        const int c = (i & 15) << 2;
        float4 v4 = *reinterpret_cast<const float4*>(qbase + r * D_ + c);
        Qs[r * 65 + c]     = v4.x;
        Qs[r * 65 + c + 1] = v4.y;
        Qs[r * 65 + c + 2] = v4.z;
        Qs[r * 65 + c + 3] = v4.w;
    }

    float o[4][8];
    float m[4], l[4];
#pragma unroll
    for (int i = 0; i < 4; i++) {
        m[i] = -1e30f; l[i] = 0.f;
#pragma unroll
        for (int j = 0; j < 8; j++) o[i][j] = 0.f;
    }

    for (int kt = 0; kt <= qtile; kt++) {
        __syncthreads();
        for (int i = tid; i < 64 * D_ / 4; i += 128) {
            const int r = i >> 4;
            const int c = (i & 15) << 2;
            float4 k4 = *reinterpret_cast<const float4*>(kbase + (size_t)(kt * 64 + r) * D_ + c);
            KPs[r * 65 + c]     = k4.x;
            KPs[r * 65 + c + 1] = k4.y;
            KPs[r * 65 + c + 2] = k4.z;
            KPs[r * 65 + c + 3] = k4.w;
            float4 v4 = *reinterpret_cast<const float4*>(vbase + (size_t)(kt * 64 + r) * D_ + c);
            Vs[r * 65 + c]     = v4.x;
            Vs[r * 65 + c + 1] = v4.y;
            Vs[r * 65 + c + 2] = v4.z;
            Vs[r * 65 + c + 3] = v4.w;
        }
        __syncthreads();

        float sc[4][8];
#pragma unroll
        for (int i = 0; i < 4; i++)
#pragma unroll
            for (int j = 0; j < 8; j++) sc[i][j] = 0.f;

#pragma unroll 8
        for (int d = 0; d < D_; d++) {
            float qa[4], kb[8];
#pragma unroll
            for (int i = 0; i < 4; i++) qa[i] = Qs[(ty * 4 + i) * 65 + d];
#pragma unroll
            for (int j = 0; j < 8; j++) kb[j] = KPs[(tx * 8 + j) * 65 + d];
#pragma unroll
            for (int i = 0; i < 4; i++)
#pragma unroll
                for (int j = 0; j < 8; j++)
                    sc[i][j] = fmaf(qa[i], kb[j], sc[i][j]);
        }

        const bool diag = (kt == qtile);
#pragma unroll
        for (int i = 0; i < 4; i++) {
            const int qgl = qtile * 64 + ty * 4 + i;
            float rmax = -1e30f;
#pragma unroll
            for (int j = 0; j < 8; j++) {
                float sv = sc[i][j] * 0.125f;
                if (diag && (kt * 64 + tx * 8 + j) > qgl) sv = -1e30f;
                sc[i][j] = sv;
                rmax = fmaxf(rmax, sv);
            }
            rmax = fmaxf(rmax, __shfl_xor_sync(0xffffffffu, rmax, 1));
            rmax = fmaxf(rmax, __shfl_xor_sync(0xffffffffu, rmax, 2));
            rmax = fmaxf(rmax, __shfl_xor_sync(0xffffffffu, rmax, 4));
            const float mn = fmaxf(m[i], rmax);
            const float corr = expf(m[i] - mn);
            float rsum = 0.f;
#pragma unroll
            for (int j = 0; j < 8; j++) {
                const float p = expf(sc[i][j] - mn);
                sc[i][j] = p;
                rsum += p;
            }
            rsum += __shfl_xor_sync(0xffffffffu, rsum, 1);
            rsum += __shfl_xor_sync(0xffffffffu, rsum, 2);
            rsum += __shfl_xor_sync(0xffffffffu, rsum, 4);
            l[i] = l[i] * corr + rsum;
            m[i] = mn;
#pragma unroll
            for (int j = 0; j < 8; j++) o[i][j] *= corr;
        }

        __syncthreads();
#pragma unroll
        for (int i = 0; i < 4; i++)
#pragma unroll
            for (int j = 0; j < 8; j++)
                KPs[(ty * 4 + i) * 65 + tx * 8 + j] = sc[i][j];
        __syncthreads();

#pragma unroll 4
        for (int jj = 0; jj < 64; jj++) {
            float pv[4], vb[8];
#pragma unroll
            for (int i = 0; i < 4; i++) pv[i] = KPs[(ty * 4 + i) * 65 + jj];
#pragma unroll
            for (int j = 0; j < 8; j++) vb[j] = Vs[jj * 65 + tx * 8 + j];
#pragma unroll
            for (int i = 0; i < 4; i++)
#pragma unroll
                for (int j = 0; j < 8; j++)
                    o[i][j] = fmaf(pv[i], vb[j], o[i][j]);
        }
    }

#pragma unroll
    for (int i = 0; i < 4; i++) {
        const float invl = 1.0f / l[i];
        const int qgl = qtile * 64 + ty * 4 + i;
        float* dst = ctx + ((size_t)(b * S_ + qgl)) * (NH_ * D_) + h * D_ + tx * 8;
#pragma unroll
        for (int j = 0; j < 8; j++) dst[j] = o[i][j] * invl;
    }
}

// ---------------------------------------------------------------------------
// Launch
// ---------------------------------------------------------------------------
extern "C" void kernel_launch(void* const* d_in, const int* in_sizes, int n_in,
                              void* d_out, int out_size) {
    const int*   positions = (const int*)d_in[0];
    const float* hidden    = (const float*)d_in[1];
    const float* Wqkv      = (const float*)d_in[2];
    const float* Wo        = (const float*)d_in[3];
    float* out = (float*)d_out;

    float *qkv_p, *q_p, *k_p, *v_p, *ctx_p;
    cudaGetSymbolAddress((void**)&qkv_p, g_qkv);
    cudaGetSymbolAddress((void**)&q_p,   g_q);
    cudaGetSymbolAddress((void**)&k_p,   g_k);
    cudaGetSymbolAddress((void**)&v_p,   g_v);
    cudaGetSymbolAddress((void**)&ctx_p, g_ctx);

    cudaFuncSetAttribute(gemm_tf32x3, cudaFuncAttributeMaxDynamicSharedMemorySize, GEMM_SMEM);
    cudaFuncSetAttribute(attn_kernel, cudaFuncAttributeMaxDynamicSharedMemorySize, ATTN_SMEM);

    // 1. QKV projection: [4096,2048] @ [2048,3072]  (tensor cores, 3xTF32)
    gemm_tf32x3<<<dim3(QKVF / GBN, (B_ * S_) / GBM), 256, GEMM_SMEM>>>(
        hidden, Wqkv, qkv_p, B_ * S_, QKVF, H_);

    // 2. RoPE + scatter
    {
        const int total = B_ * S_ * (NH_ + NKV_) * (D_ / 2);
        rope_scatter_kernel<<<(total + 255) / 256, 256>>>(positions);
        const int vtotal = B_ * S_ * NKV_ * D_ / 4;
        vcopy_kernel<<<(vtotal + 255) / 256, 256>>>();
    }

    // 3. Causal GQA flash attention
    attn_kernel<<<dim3(S_ / 64, NH_, B_), 128, ATTN_SMEM>>>(q_p, k_p, v_p, ctx_p);

    // 4. Output projection: [4096,2048] @ [2048,2048]  (tensor cores, 3xTF32)
    gemm_tf32x3<<<dim3(H_ / GBN, (B_ * S_) / GBM), 256, GEMM_SMEM>>>(
        ctx_p, Wo, out, B_ * S_, H_, NH_ * D_);
}

// round 3
// speedup vs baseline: 1.5333x; 1.2719x over previous
#include <cuda_runtime.h>
#include <cuda_bf16.h>
#include <math.h>
#include <stdint.h>

// Problem constants
#define B_   2
#define S_   2048
#define H_   2048
#define NH_  32
#define NKV_ 8
#define D_   64
#define QKVF ((NH_ + 2 * NKV_) * D_)   // 3072
#define GQA_ (NH_ / NKV_)              // 4

// ---------------------------------------------------------------------------
// Device scratch
// ---------------------------------------------------------------------------
__device__ float g_qkv[(size_t)B_ * S_ * QKVF];
__device__ float g_q  [(size_t)B_ * NH_  * S_ * D_];
__device__ float g_k  [(size_t)B_ * NKV_ * S_ * D_];
__device__ float g_v  [(size_t)B_ * NKV_ * S_ * D_];
__device__ float g_ctx[(size_t)B_ * S_ * NH_ * D_];

// ---------------------------------------------------------------------------
// Common PTX helpers
// ---------------------------------------------------------------------------
__device__ __forceinline__ void cp_async16(float* s, const float* g) {
    uint32_t sa = (uint32_t)__cvta_generic_to_shared(s);
    asm volatile("cp.async.cg.shared.global [%0], [%1], 16;\n" :: "r"(sa), "l"(g));
}
__device__ __forceinline__ void cp_commit() {
    asm volatile("cp.async.commit_group;\n");
}
__device__ __forceinline__ void tf32_split(float x, uint32_t& hi, uint32_t& lo) {
    asm("cvt.rna.tf32.f32 %0, %1;" : "=r"(hi) : "f"(x));
    lo = __float_as_uint(x - __uint_as_float(hi));
}
__device__ __forceinline__ void mma_tf32(float* c, const uint32_t* a,
                                         uint32_t b0, uint32_t b1) {
    asm volatile(
        "mma.sync.aligned.m16n8k8.row.col.f32.tf32.tf32.f32 "
        "{%0,%1,%2,%3},{%4,%5,%6,%7},{%8,%9},{%0,%1,%2,%3};"
        : "+f"(c[0]), "+f"(c[1]), "+f"(c[2]), "+f"(c[3])
        : "r"(a[0]), "r"(a[1]), "r"(a[2]), "r"(a[3]), "r"(b0), "r"(b1));
}

// ---------------------------------------------------------------------------
// Tensor-core projection GEMM (unchanged from R2): C = A @ B, 3xTF32.
// ---------------------------------------------------------------------------
#define GBM 128
#define GBN 128
#define GBK 32
#define ASTR 36
#define BSTR 136
#define A_TILE_F (GBM * ASTR)
#define B_TILE_F (GBK * BSTR)
#define GEMM_SMEM ((2 * (A_TILE_F + B_TILE_F)) * 4)

__device__ __forceinline__ void gemm_load_tiles(
    float* As, float* Bs, const float* Ag, const float* Bg,
    int k0, int K, int N, int tid) {
#pragma unroll
    for (int i = 0; i < 4; i++) {
        int idx = tid + i * 256;
        int r = idx >> 3, c = (idx & 7) << 2;
        cp_async16(&As[r * ASTR + c], Ag + (size_t)r * K + k0 + c);
    }
#pragma unroll
    for (int i = 0; i < 4; i++) {
        int idx = tid + i * 256;
        int r = idx >> 5, c = (idx & 31) << 2;
        cp_async16(&Bs[r * BSTR + c], Bg + (size_t)(k0 + r) * N + c);
    }
}

__global__ __launch_bounds__(256)
void gemm_tf32x3(const float* __restrict__ A, const float* __restrict__ Bm,
                 float* __restrict__ C, int M, int N, int K) {
    extern __shared__ float sh[];
    float* As[2] = { sh, sh + A_TILE_F };
    float* Bs[2] = { sh + 2 * A_TILE_F, sh + 2 * A_TILE_F + B_TILE_F };

    const int tid  = threadIdx.x;
    const int wid  = tid >> 5;
    const int lane = tid & 31;
    const int wm = (wid & 3) * 32;
    const int wn = (wid >> 2) * 64;
    const int g  = lane >> 2;
    const int tg = lane & 3;

    const float* Ag = A + (size_t)blockIdx.y * GBM * K;
    const float* Bg = Bm + blockIdx.x * GBN;

    float acc[2][8][4];
#pragma unroll
    for (int mi = 0; mi < 2; mi++)
#pragma unroll
        for (int ni = 0; ni < 8; ni++)
#pragma unroll
            for (int r = 0; r < 4; r++) acc[mi][ni][r] = 0.f;

    const int NIT = K / GBK;
    gemm_load_tiles(As[0], Bs[0], Ag, Bg, 0, K, N, tid);
    cp_commit();

    for (int it = 0; it < NIT; ++it) {
        const int cur = it & 1;
        if (it + 1 < NIT) {
            gemm_load_tiles(As[cur ^ 1], Bs[cur ^ 1], Ag, Bg, (it + 1) * GBK, K, N, tid);
            cp_commit();
            asm volatile("cp.async.wait_group 1;\n");
        } else {
            asm volatile("cp.async.wait_group 0;\n");
        }
        __syncthreads();

        const float* Ac = As[cur];
        const float* Bc = Bs[cur];
#pragma unroll
        for (int ks = 0; ks < 4; ks++) {
            const int k0 = ks * 8;
            uint32_t ah[2][4], al[2][4];
#pragma unroll
            for (int mi = 0; mi < 2; mi++) {
                const int mr = wm + mi * 16;
                float a0 = Ac[(mr + g)     * ASTR + k0 + tg];
                float a1 = Ac[(mr + g + 8) * ASTR + k0 + tg];
                float a2 = Ac[(mr + g)     * ASTR + k0 + tg + 4];
                float a3 = Ac[(mr + g + 8) * ASTR + k0 + tg + 4];
                tf32_split(a0, ah[mi][0], al[mi][0]);
                tf32_split(a1, ah[mi][1], al[mi][1]);
                tf32_split(a2, ah[mi][2], al[mi][2]);
                tf32_split(a3, ah[mi][3], al[mi][3]);
            }
#pragma unroll
            for (int ni = 0; ni < 8; ni++) {
                const int nc = wn + ni * 8 + g;
                float b0 = Bc[(k0 + tg)     * BSTR + nc];
                float b1 = Bc[(k0 + tg + 4) * BSTR + nc];
                uint32_t bh0, bl0, bh1, bl1;
                tf32_split(b0, bh0, bl0);
                tf32_split(b1, bh1, bl1);
#pragma unroll
                for (int mi = 0; mi < 2; mi++) {
                    mma_tf32(acc[mi][ni], ah[mi], bh0, bh1);
                    mma_tf32(acc[mi][ni], al[mi], bh0, bh1);
                    mma_tf32(acc[mi][ni], ah[mi], bl0, bl1);
                }
            }
        }
        __syncthreads();
    }

#pragma unroll
    for (int mi = 0; mi < 2; mi++) {
        const int row = blockIdx.y * GBM + wm + mi * 16 + g;
#pragma unroll
        for (int ni = 0; ni < 8; ni++) {
            const int col = blockIdx.x * GBN + wn + ni * 8 + 2 * tg;
            float2 v01 = make_float2(acc[mi][ni][0], acc[mi][ni][1]);
            float2 v23 = make_float2(acc[mi][ni][2], acc[mi][ni][3]);
            *reinterpret_cast<float2*>(C + (size_t)row * N + col) = v01;
            *reinterpret_cast<float2*>(C + (size_t)(row + 8) * N + col) = v23;
        }
    }
}

// ---------------------------------------------------------------------------
// RoPE + scatter (unchanged)
// ---------------------------------------------------------------------------
__global__ void rope_scatter_kernel(const int* __restrict__ positions) {
    const int total = B_ * S_ * (NH_ + NKV_) * (D_ / 2);
    int idx = blockIdx.x * blockDim.x + threadIdx.x;
    if (idx >= total) return;

    const int d = idx & 31;
    int t = idx >> 5;
    const int h = t % (NH_ + NKV_); t /= (NH_ + NKV_);
    const int s = t % S_;
    const int b = t / S_;

    const float pos = (float)positions[s];
    const float inv = powf(10000.0f, -(float)(2 * d) / (float)D_);
    const float freq = pos * inv;
    const double dr = (double)freq;
    const double kq = floor(dr * 0.15915494309189534 + 0.5);
    const float  rr = (float)(dr - kq * 6.283185307179586477);
    float sn, cs;
    sincosf(rr, &sn, &cs);

    const float* base = g_qkv + (size_t)(b * S_ + s) * QKVF;
    float x0, x1;
    float* dst;
    if (h < NH_) {
        x0 = base[h * D_ + d];
        x1 = base[h * D_ + d + 32];
        dst = g_q + (((size_t)(b * NH_ + h)) * S_ + s) * D_;
    } else {
        const int hk = h - NH_;
        x0 = base[NH_ * D_ + hk * D_ + d];
        x1 = base[NH_ * D_ + hk * D_ + d + 32];
        dst = g_k + (((size_t)(b * NKV_ + hk)) * S_ + s) * D_;
    }
    dst[d]      = x0 * cs - x1 * sn;
    dst[d + 32] = x1 * cs + x0 * sn;
}

__global__ void vcopy_kernel() {
    const int total = B_ * S_ * NKV_ * D_ / 4;
    int idx = blockIdx.x * blockDim.x + threadIdx.x;
    if (idx >= total) return;
    const int c4 = idx & (D_ / 4 - 1);
    int t = idx >> 4;
    const int h = t % NKV_; t /= NKV_;
    const int s = t % S_;
    const int b = t / S_;
    const float4 v = *reinterpret_cast<const float4*>(
        g_qkv + (size_t)(b * S_ + s) * QKVF + (NH_ + NKV_) * D_ + h * D_ + c4 * 4);
    *reinterpret_cast<float4*>(
        g_v + (((size_t)(b * NKV_ + h)) * S_ + s) * D_ + c4 * 4) = v;
}

// ---------------------------------------------------------------------------
// Tensor-core causal flash attention (3xTF32 MMA, online softmax).
// Block: 128 threads (4 warps), 64 q-rows per block, 64-key tiles.
// Warp w owns q rows [w*16, w*16+16). cp.async double-buffered K/V.
// smem strides: Q/P/K = 68 (A & "row=g" B patterns conflict-free),
//               V = 72 ("row=tg" B pattern conflict-free).
// ---------------------------------------------------------------------------
#define QS_STR 68
#define KS_STR 68
#define PS_STR 68
#define VS_STR 72
#define Q_F   (64 * QS_STR)          // 4352
#define P_F   (64 * PS_STR)          // 4352
#define K_F   (64 * KS_STR)          // 4352
#define V_F   (64 * VS_STR)          // 4608
#define ATTN_SMEM ((Q_F + P_F + 2 * K_F + 2 * V_F) * 4)   // 106496 B

__device__ __forceinline__ void attn_load_kv(
    float* Kd, float* Vd, const float* kbase, const float* vbase,
    int kt, int tid) {
#pragma unroll
    for (int i = 0; i < 8; i++) {
        int idx = tid + i * 128;
        int r = idx >> 4, c = (idx & 15) << 2;
        cp_async16(&Kd[r * KS_STR + c], kbase + (size_t)(kt * 64 + r) * D_ + c);
    }
#pragma unroll
    for (int i = 0; i < 8; i++) {
        int idx = tid + i * 128;
        int r = idx >> 4, c = (idx & 15) << 2;
        cp_async16(&Vd[r * VS_STR + c], vbase + (size_t)(kt * 64 + r) * D_ + c);
    }
}

__global__ __launch_bounds__(128)
void attn_kernel(const float* __restrict__ qg, const float* __restrict__ kg,
                 const float* __restrict__ vg, float* __restrict__ ctx) {
    extern __shared__ float sm[];
    float* Qs    = sm;
    float* Ps    = sm + Q_F;
    float* Ks[2] = { sm + Q_F + P_F, sm + Q_F + P_F + K_F };
    float* Vs[2] = { sm + Q_F + P_F + 2 * K_F, sm + Q_F + P_F + 2 * K_F + V_F };

    const int qtile = gridDim.x - 1 - blockIdx.x;   // heavy tiles first
    const int h = blockIdx.y;
    const int b = blockIdx.z;
    const int kvh = h / GQA_;
    const int q0 = qtile * 64;

    const float* qbase = qg + (((size_t)(b * NH_ + h)) * S_ + q0) * D_;
    const float* kbase = kg + ((size_t)(b * NKV_ + kvh)) * S_ * D_;
    const float* vbase = vg + ((size_t)(b * NKV_ + kvh)) * S_ * D_;

    const int tid  = threadIdx.x;
    const int wid  = tid >> 5;
    const int lane = tid & 31;
    const int g    = lane >> 2;
    const int tg   = lane & 3;
    const int wm   = wid * 16;          // warp's q-row offset in tile

    // Load Q tile (scaled by 1/sqrt(D) = 0.125)
#pragma unroll
    for (int i = 0; i < 8; i++) {
        int idx = tid + i * 128;
        int r = idx >> 4, c = (idx & 15) << 2;
        float4 v4 = *reinterpret_cast<const float4*>(qbase + (size_t)r * D_ + c);
        Qs[r * QS_STR + c]     = v4.x * 0.125f;
        Qs[r * QS_STR + c + 1] = v4.y * 0.125f;
        Qs[r * QS_STR + c + 2] = v4.z * 0.125f;
        Qs[r * QS_STR + c + 3] = v4.w * 0.125f;
    }

    attn_load_kv(Ks[0], Vs[0], kbase, vbase, 0, tid);
    cp_commit();

    float oacc[8][4];
    float m0 = -1e30f, m1 = -1e30f, l0 = 0.f, l1 = 0.f;
#pragma unroll
    for (int ni = 0; ni < 8; ni++)
#pragma unroll
        for (int r = 0; r < 4; r++) oacc[ni][r] = 0.f;

    const int gq0 = q0 + wm + g;        // global q row for c0/c1
    const int gq1 = gq0 + 8;            // for c2/c3

    for (int kt = 0; kt <= qtile; kt++) {
        const int cur = kt & 1;
        asm volatile("cp.async.wait_group 0;\n");
        __syncthreads();
        if (kt + 1 <= qtile) {
            attn_load_kv(Ks[cur ^ 1], Vs[cur ^ 1], kbase, vbase, kt + 1, tid);
            cp_commit();
        }

        const float* Kc = Ks[cur];
        const float* Vc = Vs[cur];

        // ---- S = Q @ K^T (3xTF32) ----
        float sacc[8][4];
#pragma unroll
        for (int ni = 0; ni < 8; ni++)
#pragma unroll
            for (int r = 0; r < 4; r++) sacc[ni][r] = 0.f;

#pragma unroll
        for (int ks = 0; ks < 8; ks++) {
            const int k0 = ks * 8;
            uint32_t ah[4], al[4];
            tf32_split(Qs[(wm + g)     * QS_STR + k0 + tg],     ah[0], al[0]);
            tf32_split(Qs[(wm + g + 8) * QS_STR + k0 + tg],     ah[1], al[1]);
            tf32_split(Qs[(wm + g)     * QS_STR + k0 + tg + 4], ah[2], al[2]);
            tf32_split(Qs[(wm + g + 8) * QS_STR + k0 + tg + 4], ah[3], al[3]);
#pragma unroll
            for (int ni = 0; ni < 8; ni++) {
                float b0 = Kc[(ni * 8 + g) * KS_STR + k0 + tg];
                float b1 = Kc[(ni * 8 + g) * KS_STR + k0 + tg + 4];
                uint32_t bh0, bl0, bh1, bl1;
                tf32_split(b0, bh0, bl0);
                tf32_split(b1, bh1, bl1);
                mma_tf32(sacc[ni], ah, bh0, bh1);
                mma_tf32(sacc[ni], al, bh0, bh1);
                mma_tf32(sacc[ni], ah, bl0, bl1);
            }
        }

        // ---- causal mask (diag tile only) ----
        if (kt == qtile) {
#pragma unroll
            for (int ni = 0; ni < 8; ni++) {
                const int col = kt * 64 + ni * 8 + 2 * tg;
                if (col     > gq0) sacc[ni][0] = -1e30f;
                if (col + 1 > gq0) sacc[ni][1] = -1e30f;
                if (col     > gq1) sacc[ni][2] = -1e30f;
                if (col + 1 > gq1) sacc[ni][3] = -1e30f;
            }
        }

        // ---- online softmax ----
        float mx0 = -1e30f, mx1 = -1e30f;
#pragma unroll
        for (int ni = 0; ni < 8; ni++) {
            mx0 = fmaxf(mx0, fmaxf(sacc[ni][0], sacc[ni][1]));
            mx1 = fmaxf(mx1, fmaxf(sacc[ni][2], sacc[ni][3]));
        }
        mx0 = fmaxf(mx0, __shfl_xor_sync(0xffffffffu, mx0, 1));
        mx0 = fmaxf(mx0, __shfl_xor_sync(0xffffffffu, mx0, 2));
        mx1 = fmaxf(mx1, __shfl_xor_sync(0xffffffffu, mx1, 1));
        mx1 = fmaxf(mx1, __shfl_xor_sync(0xffffffffu, mx1, 2));

        const float mn0 = fmaxf(m0, mx0);
        const float mn1 = fmaxf(m1, mx1);
        const float corr0 = __expf(m0 - mn0);
        const float corr1 = __expf(m1 - mn1);
        float rs0 = 0.f, rs1 = 0.f;
#pragma unroll
        for (int ni = 0; ni < 8; ni++) {
            float p0 = __expf(sacc[ni][0] - mn0);
            float p1 = __expf(sacc[ni][1] - mn0);
            float p2 = __expf(sacc[ni][2] - mn1);
            float p3 = __expf(sacc[ni][3] - mn1);
            sacc[ni][0] = p0; sacc[ni][1] = p1;
            sacc[ni][2] = p2; sacc[ni][3] = p3;
            rs0 += p0 + p1;
            rs1 += p2 + p3;
        }
        rs0 += __shfl_xor_sync(0xffffffffu, rs0, 1);
        rs0 += __shfl_xor_sync(0xffffffffu, rs0, 2);
        rs1 += __shfl_xor_sync(0xffffffffu, rs1, 1);
        rs1 += __shfl_xor_sync(0xffffffffu, rs1, 2);
        l0 = l0 * corr0 + rs0;
        l1 = l1 * corr1 + rs1;
        m0 = mn0;
        m1 = mn1;
#pragma unroll
        for (int ni = 0; ni < 8; ni++) {
            oacc[ni][0] *= corr0;
            oacc[ni][1] *= corr0;
            oacc[ni][2] *= corr1;
            oacc[ni][3] *= corr1;
        }

        // ---- store P to smem (A-operand layout for PV) ----
#pragma unroll
        for (int ni = 0; ni < 8; ni++) {
            const int c = ni * 8 + 2 * tg;
            *reinterpret_cast<float2*>(&Ps[(wm + g)     * PS_STR + c]) =
                make_float2(sacc[ni][0], sacc[ni][1]);
            *reinterpret_cast<float2*>(&Ps[(wm + g + 8) * PS_STR + c]) =
                make_float2(sacc[ni][2], sacc[ni][3]);
        }
        __syncthreads();

        // ---- O += P @ V (3xTF32) ----
#pragma unroll
        for (int ks = 0; ks < 8; ks++) {
            const int k0 = ks * 8;
            uint32_t ah[4], al[4];
            tf32_split(Ps[(wm + g)     * PS_STR + k0 + tg],     ah[0], al[0]);
            tf32_split(Ps[(wm + g + 8) * PS_STR + k0 + tg],     ah[1], al[1]);
            tf32_split(Ps[(wm + g)     * PS_STR + k0 + tg + 4], ah[2], al[2]);
            tf32_split(Ps[(wm + g + 8) * PS_STR + k0 + tg + 4], ah[3], al[3]);
#pragma unroll
            for (int ni = 0; ni < 8; ni++) {
                float b0 = Vc[(k0 + tg)     * VS_STR + ni * 8 + g];
                float b1 = Vc[(k0 + tg + 4) * VS_STR + ni * 8 + g];
                uint32_t bh0, bl0, bh1, bl1;
                tf32_split(b0, bh0, bl0);
                tf32_split(b1, bh1, bl1);
                mma_tf32(oacc[ni], ah, bh0, bh1);
                mma_tf32(oacc[ni], al, bh0, bh1);
                mma_tf32(oacc[ni], ah, bl0, bl1);
            }
        }
    }

    // ---- normalize + write ctx [b][s][h*D+d] ----
    const float il0 = 1.0f / l0;
    const float il1 = 1.0f / l1;
    float* dst0 = ctx + ((size_t)(b * S_ + gq0)) * (NH_ * D_) + h * D_;
    float* dst1 = ctx + ((size_t)(b * S_ + gq1)) * (NH_ * D_) + h * D_;
#pragma unroll
    for (int ni = 0; ni < 8; ni++) {
        const int c = ni * 8 + 2 * tg;
        *reinterpret_cast<float2*>(dst0 + c) =
            make_float2(oacc[ni][0] * il0, oacc[ni][1] * il0);
        *reinterpret_cast<float2*>(dst1 + c) =
            make_float2(oacc[ni][2] * il1, oacc[ni][3] * il1);
    }
}

// ---------------------------------------------------------------------------
// Launch
// ---------------------------------------------------------------------------
extern "C" void kernel_launch(void* const* d_in, const int* in_sizes, int n_in,
                              void* d_out, int out_size) {
    const int*   positions = (const int*)d_in[0];
    const float* hidden    = (const float*)d_in[1];
    const float* Wqkv      = (const float*)d_in[2];
    const float* Wo        = (const float*)d_in[3];
    float* out = (float*)d_out;

    float *qkv_p, *q_p, *k_p, *v_p, *ctx_p;
    cudaGetSymbolAddress((void**)&qkv_p, g_qkv);
    cudaGetSymbolAddress((void**)&q_p,   g_q);
    cudaGetSymbolAddress((void**)&k_p,   g_k);
    cudaGetSymbolAddress((void**)&v_p,   g_v);
    cudaGetSymbolAddress((void**)&ctx_p, g_ctx);

    cudaFuncSetAttribute(gemm_tf32x3, cudaFuncAttributeMaxDynamicSharedMemorySize, GEMM_SMEM);
    cudaFuncSetAttribute(attn_kernel, cudaFuncAttributeMaxDynamicSharedMemorySize, ATTN_SMEM);

    // 1. QKV projection
    gemm_tf32x3<<<dim3(QKVF / GBN, (B_ * S_) / GBM), 256, GEMM_SMEM>>>(
        hidden, Wqkv, qkv_p, B_ * S_, QKVF, H_);

    // 2. RoPE + scatter
    {
        const int total = B_ * S_ * (NH_ + NKV_) * (D_ / 2);
        rope_scatter_kernel<<<(total + 255) / 256, 256>>>(positions);
        const int vtotal = B_ * S_ * NKV_ * D_ / 4;
        vcopy_kernel<<<(vtotal + 255) / 256, 256>>>();
    }

    // 3. Causal GQA flash attention (tensor cores)
    attn_kernel<<<dim3(S_ / 64, NH_, B_), 128, ATTN_SMEM>>>(q_p, k_p, v_p, ctx_p);

    // 4. Output projection
    gemm_tf32x3<<<dim3(H_ / GBN, (B_ * S_) / GBM), 256, GEMM_SMEM>>>(
        ctx_p, Wo, out, B_ * S_, H_, NH_ * D_);
}

// round 5
// speedup vs baseline: 2.6615x; 1.7358x over previous
#include <cuda_runtime.h>
#include <cuda_bf16.h>
#include <math.h>
#include <stdint.h>

#define B_   2
#define S_   2048
#define H_   2048
#define NH_  32
#define NKV_ 8
#define D_   64
#define QKVF ((NH_ + 2 * NKV_) * D_)   // 3072
#define GQA_ (NH_ / NKV_)              // 4

typedef __nv_bfloat16 bf16;

// ---------------------------------------------------------------------------
// Device scratch
// ---------------------------------------------------------------------------
__device__ float g_qkv[(size_t)B_ * S_ * QKVF];
__device__ bf16 g_hid_hi[(size_t)B_ * S_ * H_];
__device__ bf16 g_hid_lo[(size_t)B_ * S_ * H_];
__device__ bf16 g_wqkv_hi[(size_t)QKVF * H_];   // transposed [N][K]
__device__ bf16 g_wqkv_lo[(size_t)QKVF * H_];
__device__ bf16 g_wo_hi[(size_t)H_ * H_];       // transposed [N][K]
__device__ bf16 g_wo_lo[(size_t)H_ * H_];
__device__ bf16 g_q_hi[(size_t)B_ * NH_ * S_ * D_];   // [b][h][s][d], pre-scaled 0.125
__device__ bf16 g_q_lo[(size_t)B_ * NH_ * S_ * D_];
__device__ bf16 g_k_hi[(size_t)B_ * NKV_ * S_ * D_];
__device__ bf16 g_k_lo[(size_t)B_ * NKV_ * S_ * D_];
__device__ bf16 g_vt_hi[(size_t)B_ * NKV_ * D_ * S_]; // [b][kh][d][s] (transposed)
__device__ bf16 g_vt_lo[(size_t)B_ * NKV_ * D_ * S_];
__device__ bf16 g_ctx_hi[(size_t)B_ * S_ * NH_ * D_]; // [b*s][NH*D]
__device__ bf16 g_ctx_lo[(size_t)B_ * S_ * NH_ * D_];

// ---------------------------------------------------------------------------
// Helpers
// ---------------------------------------------------------------------------
__device__ __forceinline__ void cp_async16(void* s, const void* g) {
    uint32_t sa = (uint32_t)__cvta_generic_to_shared(s);
    asm volatile("cp.async.cg.shared.global [%0], [%1], 16;\n" :: "r"(sa), "l"(g));
}
__device__ __forceinline__ void cp_commit() {
    asm volatile("cp.async.commit_group;\n");
}
// pack (x -> element0/low, y -> element1/high)
__device__ __forceinline__ uint32_t pack2(float x, float y) {
    uint32_t r;
    asm("cvt.rn.bf16x2.f32 %0, %1, %2;" : "=r"(r) : "f"(y), "f"(x));
    return r;
}
__device__ __forceinline__ void split2(float x, float y, uint32_t& hi, uint32_t& lo) {
    hi = pack2(x, y);
    float hx = __uint_as_float(hi << 16);
    float hy = __uint_as_float(hi & 0xFFFF0000u);
    lo = pack2(x - hx, y - hy);
}
__device__ __forceinline__ void mma_bf16(float* c, const uint32_t* a,
                                         uint32_t b0, uint32_t b1) {
    asm volatile(
        "mma.sync.aligned.m16n8k16.row.col.f32.bf16.bf16.f32 "
        "{%0,%1,%2,%3},{%4,%5,%6,%7},{%8,%9},{%0,%1,%2,%3};"
        : "+f"(c[0]), "+f"(c[1]), "+f"(c[2]), "+f"(c[3])
        : "r"(a[0]), "r"(a[1]), "r"(a[2]), "r"(a[3]), "r"(b0), "r"(b1));
}

// ---------------------------------------------------------------------------
// Pre-pass: split fp32 -> bf16 hi/lo (same layout)
// ---------------------------------------------------------------------------
__global__ void split_kernel(const float* __restrict__ src,
                             uint32_t* __restrict__ hi, uint32_t* __restrict__ lo,
                             int n2) {
    int i = blockIdx.x * blockDim.x + threadIdx.x;
    if (i >= n2) return;
    float2 v = reinterpret_cast<const float2*>(src)[i];
    uint32_t h, l;
    split2(v.x, v.y, h, l);
    hi[i] = h;
    lo[i] = l;
}

// Pre-pass: split + transpose fp32 [K][N] -> bf16 hi/lo [N][K]
__global__ void split_transpose_kernel(const float* __restrict__ src,
                                       bf16* __restrict__ dhi, bf16* __restrict__ dlo,
                                       int K, int N) {
    __shared__ float t[32][33];
    const int n0 = blockIdx.x * 32, k0 = blockIdx.y * 32;
    const int tx = threadIdx.x, ty = threadIdx.y;   // (32, 8)
#pragma unroll
    for (int r = 0; r < 4; r++)
        t[ty + 8 * r][tx] = src[(size_t)(k0 + ty + 8 * r) * N + n0 + tx];
    __syncthreads();
#pragma unroll
    for (int r = 0; r < 4; r++) {
        float x = t[tx][ty + 8 * r];
        bf16 h = __float2bfloat16(x);
        float hf = __bfloat162float(h);
        size_t off = (size_t)(n0 + ty + 8 * r) * K + k0 + tx;
        dhi[off] = h;
        dlo[off] = __float2bfloat16(x - hf);
    }
}

// ---------------------------------------------------------------------------
// bf16x3 GEMM: C[M,N](fp32) = A[M,K] @ Bt[N,K]^T, pre-split bf16 operands.
// 128x128x32 block tile, 256 threads, warp tile 32x64, cp.async 2-stage.
// ---------------------------------------------------------------------------
#define PW 20                        // words per 32-bf16 row (16 + 4 pad)
#define TILE_W (128 * PW)            // 2560 words per tile-array
#define GSMEM (2 * 4 * TILE_W * 4)   // 81920 B

__global__ __launch_bounds__(256)
void gemm_bf16x3(const bf16* __restrict__ Ahi, const bf16* __restrict__ Alo,
                 const bf16* __restrict__ Bhi, const bf16* __restrict__ Blo,
                 float* __restrict__ C, int M, int N, int K) {
    extern __shared__ uint32_t sw[];

    const int tid  = threadIdx.x;
    const int wid  = tid >> 5;
    const int lane = tid & 31;
    const int g  = lane >> 2;
    const int tg = lane & 3;
    const int wm = (wid & 3) * 32;
    const int wn = (wid >> 2) * 64;

    const bf16* gptr[4] = {
        Ahi + (size_t)blockIdx.y * 128 * K,
        Alo + (size_t)blockIdx.y * 128 * K,
        Bhi + (size_t)blockIdx.x * 128 * K,
        Blo + (size_t)blockIdx.x * 128 * K
    };

    float acc[2][8][4];
#pragma unroll
    for (int mi = 0; mi < 2; mi++)
#pragma unroll
        for (int ni = 0; ni < 8; ni++)
#pragma unroll
            for (int r = 0; r < 4; r++) acc[mi][ni][r] = 0.f;

#define GEMM_LOAD(st, k0)                                                     \
    {                                                                          \
        _Pragma("unroll")                                                      \
        for (int j = 0; j < 8; j++) {                                          \
            int idx = tid + j * 256;                                           \
            int arr = j >> 1;                                                  \
            int r = (idx >> 2) & 127, c = idx & 3;                             \
            cp_async16(sw + (st) * (4 * TILE_W) + arr * TILE_W + r * PW + c * 4, \
                       gptr[arr] + (size_t)r * K + (k0) + c * 8);              \
        }                                                                      \
        cp_commit();                                                           \
    }

    const int NIT = K / 32;
    GEMM_LOAD(0, 0);

    for (int it = 0; it < NIT; ++it) {
        const int cur = it & 1;
        if (it + 1 < NIT) {
            GEMM_LOAD(cur ^ 1, (it + 1) * 32);
            asm volatile("cp.async.wait_group 1;\n");
        } else {
            asm volatile("cp.async.wait_group 0;\n");
        }
        __syncthreads();

        const uint32_t* SAh = sw + cur * (4 * TILE_W);
        const uint32_t* SAl = SAh + TILE_W;
        const uint32_t* SBh = SAh + 2 * TILE_W;
        const uint32_t* SBl = SAh + 3 * TILE_W;

#pragma unroll
        for (int ch = 0; ch < 2; ch++) {
            const int kw = ch * 8;
            uint32_t ah[2][4], al[2][4];
#pragma unroll
            for (int mi = 0; mi < 2; mi++) {
                const int r0 = wm + mi * 16 + g;
                ah[mi][0] = SAh[r0 * PW + kw + tg];
                ah[mi][1] = SAh[(r0 + 8) * PW + kw + tg];
                ah[mi][2] = SAh[r0 * PW + kw + tg + 4];
                ah[mi][3] = SAh[(r0 + 8) * PW + kw + tg + 4];
                al[mi][0] = SAl[r0 * PW + kw + tg];
                al[mi][1] = SAl[(r0 + 8) * PW + kw + tg];
                al[mi][2] = SAl[r0 * PW + kw + tg + 4];
                al[mi][3] = SAl[(r0 + 8) * PW + kw + tg + 4];
            }
#pragma unroll
            for (int ni = 0; ni < 8; ni++) {
                const int rn = wn + ni * 8 + g;
                uint32_t bh0 = SBh[rn * PW + kw + tg];
                uint32_t bh1 = SBh[rn * PW + kw + tg + 4];
                uint32_t bl0 = SBl[rn * PW + kw + tg];
                uint32_t bl1 = SBl[rn * PW + kw + tg + 4];
#pragma unroll
                for (int mi = 0; mi < 2; mi++) {
                    mma_bf16(acc[mi][ni], ah[mi], bh0, bh1);
                    mma_bf16(acc[mi][ni], al[mi], bh0, bh1);
                    mma_bf16(acc[mi][ni], ah[mi], bl0, bl1);
                }
            }
        }
        __syncthreads();
    }

#pragma unroll
    for (int mi = 0; mi < 2; mi++) {
        const int row = blockIdx.y * 128 + wm + mi * 16 + g;
#pragma unroll
        for (int ni = 0; ni < 8; ni++) {
            const int col = blockIdx.x * 128 + wn + ni * 8 + 2 * tg;
            *reinterpret_cast<float2*>(C + (size_t)row * N + col) =
                make_float2(acc[mi][ni][0], acc[mi][ni][1]);
            *reinterpret_cast<float2*>(C + (size_t)(row + 8) * N + col) =
                make_float2(acc[mi][ni][2], acc[mi][ni][3]);
        }
    }
}

// ---------------------------------------------------------------------------
// RoPE + scatter, emitting pre-split bf16 (Q pre-scaled by 1/8)
// ---------------------------------------------------------------------------
__global__ void rope_scatter_kernel(const int* __restrict__ positions) {
    const int total = B_ * S_ * (NH_ + NKV_) * (D_ / 2);
    int idx = blockIdx.x * blockDim.x + threadIdx.x;
    if (idx >= total) return;

    const int d = idx & 31;
    int t = idx >> 5;
    const int h = t % (NH_ + NKV_); t /= (NH_ + NKV_);
    const int s = t % S_;
    const int b = t / S_;

    const float pos = (float)positions[s];
    const float inv = powf(10000.0f, -(float)(2 * d) / (float)D_);
    const float freq = pos * inv;
    const double dr = (double)freq;
    const double kq = floor(dr * 0.15915494309189534 + 0.5);
    const float  rr = (float)(dr - kq * 6.283185307179586477);
    float sn, cs;
    sincosf(rr, &sn, &cs);

    const float* base = g_qkv + (size_t)(b * S_ + s) * QKVF;
    float x0, x1, scale;
    bf16 *dhi, *dlo;
    if (h < NH_) {
        x0 = base[h * D_ + d];
        x1 = base[h * D_ + d + 32];
        size_t off = (((size_t)(b * NH_ + h)) * S_ + s) * D_;
        dhi = g_q_hi + off; dlo = g_q_lo + off;
        scale = 0.125f;
    } else {
        const int hk = h - NH_;
        x0 = base[NH_ * D_ + hk * D_ + d];
        x1 = base[NH_ * D_ + hk * D_ + d + 32];
        size_t off = (((size_t)(b * NKV_ + hk)) * S_ + s) * D_;
        dhi = g_k_hi + off; dlo = g_k_lo + off;
        scale = 1.0f;
    }
    float v0 = (x0 * cs - x1 * sn) * scale;
    float v1 = (x1 * cs + x0 * sn) * scale;
    bf16 h0 = __float2bfloat16(v0);
    bf16 h1 = __float2bfloat16(v1);
    dhi[d]      = h0;
    dhi[d + 32] = h1;
    dlo[d]      = __float2bfloat16(v0 - __bfloat162float(h0));
    dlo[d + 32] = __float2bfloat16(v1 - __bfloat162float(h1));
}

// V: split + transpose into [b][kh][d][s]
__global__ void vtranspose_kernel() {
    __shared__ float t[32][65];
    const int s0 = blockIdx.x * 32;
    const int kh = blockIdx.y;
    const int b  = blockIdx.z;
    const int tid = threadIdx.x;

    const float* src = g_qkv + (size_t)b * S_ * QKVF + (NH_ + NKV_) * D_ + kh * D_;
#pragma unroll
    for (int j = 0; j < 8; j++) {
        int e = tid + j * 256;
        int s = e >> 6, d = e & 63;
        t[s][d] = src[(size_t)(s0 + s) * QKVF + d];
    }
    __syncthreads();

    bf16* dhi = g_vt_hi + ((size_t)(b * NKV_ + kh)) * D_ * S_;
    bf16* dlo = g_vt_lo + ((size_t)(b * NKV_ + kh)) * D_ * S_;
#pragma unroll
    for (int j = 0; j < 8; j++) {
        int e = tid + j * 256;
        int d = e >> 5, s = e & 31;
        float x = t[s][d];
        bf16 h = __float2bfloat16(x);
        dhi[(size_t)d * S_ + s0 + s] = h;
        dlo[(size_t)d * S_ + s0 + s] = __float2bfloat16(x - __bfloat162float(h));
    }
}

// ---------------------------------------------------------------------------
// bf16x3 causal flash attention. 128 threads, 64 q-rows/block, 64-key tiles.
// smem tiles (uint32 words, 64 rows x 36-word stride):
//  0 Qhi 1 Qlo 2 Phi 3 Plo | 4+2st Khi 5+2st Klo | 8+2st Vhi 9+2st Vlo
// ---------------------------------------------------------------------------
#define AW 36
#define AT_W (64 * AW)                 // 2304 words
#define ATTN_SMEM (12 * AT_W * 4)      // 110592 B

__global__ __launch_bounds__(128)
void attn_kernel(float* /*unused*/) {
    extern __shared__ uint32_t sw[];

    const int qtile = gridDim.x - 1 - blockIdx.x;
    const int h = blockIdx.y;
    const int b = blockIdx.z;
    const int kvh = h / GQA_;
    const int q0 = qtile * 64;

    const bf16* qh_g = g_q_hi + (((size_t)(b * NH_ + h)) * S_ + q0) * D_;
    const bf16* ql_g = g_q_lo + (((size_t)(b * NH_ + h)) * S_ + q0) * D_;
    const bf16* kh_g = g_k_hi + ((size_t)(b * NKV_ + kvh)) * S_ * D_;
    const bf16* kl_g = g_k_lo + ((size_t)(b * NKV_ + kvh)) * S_ * D_;
    const bf16* vh_g = g_vt_hi + ((size_t)(b * NKV_ + kvh)) * D_ * S_;
    const bf16* vl_g = g_vt_lo + ((size_t)(b * NKV_ + kvh)) * D_ * S_;

    const int tid  = threadIdx.x;
    const int wid  = tid >> 5;
    const int lane = tid & 31;
    const int g  = lane >> 2;
    const int tg = lane & 3;
    const int wm = wid * 16;

    // Q tile (hi+lo): 1024 16B chunks
#pragma unroll
    for (int j = 0; j < 8; j++) {
        int idx = tid + j * 128;
        int r = (idx >> 3) & 63, c = idx & 7;
        const bf16* src = (j >> 2) ? ql_g : qh_g;
        cp_async16(sw + (j >> 2) * AT_W + r * AW + c * 4, src + (size_t)r * D_ + c * 8);
    }
    cp_commit();

// K tiles at 4+2st,5+2st ; V tiles at 8+2st,9+2st  (fixed V base: 8, was 6)
#define ATTN_LOAD_KV(st, kt)                                                    \
    {                                                                            \
        _Pragma("unroll")                                                        \
        for (int j = 0; j < 16; j++) {                                           \
            int idx = tid + j * 128;                                              \
            int arr = j >> 2;                                                     \
            int r = (idx >> 3) & 63, c = idx & 7;                                 \
            int tile = (arr < 2 ? 4 : 8) + 2 * (st) + (arr & 1);                  \
            const bf16* src;                                                      \
            size_t goff;                                                          \
            if (arr == 0)      { src = kh_g; goff = (size_t)((kt) * 64 + r) * D_ + c * 8; } \
            else if (arr == 1) { src = kl_g; goff = (size_t)((kt) * 64 + r) * D_ + c * 8; } \
            else if (arr == 2) { src = vh_g; goff = (size_t)r * S_ + (kt) * 64 + c * 8; }   \
            else               { src = vl_g; goff = (size_t)r * S_ + (kt) * 64 + c * 8; }   \
            cp_async16(sw + tile * AT_W + r * AW + c * 4, src + goff);            \
        }                                                                         \
        cp_commit();                                                              \
    }

    ATTN_LOAD_KV(0, 0);

    float oacc[8][4];
    float m0 = -1e30f, m1 = -1e30f, l0 = 0.f, l1 = 0.f;
#pragma unroll
    for (int ni = 0; ni < 8; ni++)
#pragma unroll
        for (int r = 0; r < 4; r++) oacc[ni][r] = 0.f;

    const int gq0 = q0 + wm + g;
    const int gq1 = gq0 + 8;

    const uint32_t* Qh = sw;
    const uint32_t* Ql = sw + AT_W;
    uint32_t* Ph = sw + 2 * AT_W;
    uint32_t* Pl = sw + 3 * AT_W;

    for (int kt = 0; kt <= qtile; kt++) {
        const int cur = kt & 1;
        if (kt + 1 <= qtile) {
            ATTN_LOAD_KV(cur ^ 1, kt + 1);
            asm volatile("cp.async.wait_group 1;\n");
        } else {
            asm volatile("cp.async.wait_group 0;\n");
        }
        __syncthreads();

        const uint32_t* Kh = sw + (4 + 2 * cur) * AT_W;
        const uint32_t* Kl = sw + (5 + 2 * cur) * AT_W;
        const uint32_t* Vh = sw + (8 + 2 * cur) * AT_W;
        const uint32_t* Vl = sw + (9 + 2 * cur) * AT_W;

        // ---- S = Q @ K^T ----
        float sacc[8][4];
#pragma unroll
        for (int ni = 0; ni < 8; ni++)
#pragma unroll
            for (int r = 0; r < 4; r++) sacc[ni][r] = 0.f;

#pragma unroll
        for (int ch = 0; ch < 4; ch++) {
            const int kw = ch * 8;
            uint32_t qh[4], ql[4];
            qh[0] = Qh[(wm + g) * AW + kw + tg];
            qh[1] = Qh[(wm + g + 8) * AW + kw + tg];
            qh[2] = Qh[(wm + g) * AW + kw + tg + 4];
            qh[3] = Qh[(wm + g + 8) * AW + kw + tg + 4];
            ql[0] = Ql[(wm + g) * AW + kw + tg];
            ql[1] = Ql[(wm + g + 8) * AW + kw + tg];
            ql[2] = Ql[(wm + g) * AW + kw + tg + 4];
            ql[3] = Ql[(wm + g + 8) * AW + kw + tg + 4];
#pragma unroll
            for (int ni = 0; ni < 8; ni++) {
                const int rn = ni * 8 + g;
                uint32_t bh0 = Kh[rn * AW + kw + tg];
                uint32_t bh1 = Kh[rn * AW + kw + tg + 4];
                uint32_t bl0 = Kl[rn * AW + kw + tg];
                uint32_t bl1 = Kl[rn * AW + kw + tg + 4];
                mma_bf16(sacc[ni], qh, bh0, bh1);
                mma_bf16(sacc[ni], ql, bh0, bh1);
                mma_bf16(sacc[ni], qh, bl0, bl1);
            }
        }

        // ---- causal mask ----
        if (kt == qtile) {
#pragma unroll
            for (int ni = 0; ni < 8; ni++) {
                const int col = kt * 64 + ni * 8 + 2 * tg;
                if (col     > gq0) sacc[ni][0] = -1e30f;
                if (col + 1 > gq0) sacc[ni][1] = -1e30f;
                if (col     > gq1) sacc[ni][2] = -1e30f;
                if (col + 1 > gq1) sacc[ni][3] = -1e30f;
            }
        }

        // ---- online softmax ----
        float mx0 = -1e30f, mx1 = -1e30f;
#pragma unroll
        for (int ni = 0; ni < 8; ni++) {
            mx0 = fmaxf(mx0, fmaxf(sacc[ni][0], sacc[ni][1]));
            mx1 = fmaxf(mx1, fmaxf(sacc[ni][2], sacc[ni][3]));
        }
        mx0 = fmaxf(mx0, __shfl_xor_sync(0xffffffffu, mx0, 1));
        mx0 = fmaxf(mx0, __shfl_xor_sync(0xffffffffu, mx0, 2));
        mx1 = fmaxf(mx1, __shfl_xor_sync(0xffffffffu, mx1, 1));
        mx1 = fmaxf(mx1, __shfl_xor_sync(0xffffffffu, mx1, 2));

        const float mn0 = fmaxf(m0, mx0);
        const float mn1 = fmaxf(m1, mx1);
        const float corr0 = __expf(m0 - mn0);
        const float corr1 = __expf(m1 - mn1);
        float rs0 = 0.f, rs1 = 0.f;
#pragma unroll
        for (int ni = 0; ni < 8; ni++) {
            float p0 = __expf(sacc[ni][0] - mn0);
            float p1 = __expf(sacc[ni][1] - mn0);
            float p2 = __expf(sacc[ni][2] - mn1);
            float p3 = __expf(sacc[ni][3] - mn1);
            sacc[ni][0] = p0; sacc[ni][1] = p1;
            sacc[ni][2] = p2; sacc[ni][3] = p3;
            rs0 += p0 + p1;
            rs1 += p2 + p3;
        }
        rs0 += __shfl_xor_sync(0xffffffffu, rs0, 1);
        rs0 += __shfl_xor_sync(0xffffffffu, rs0, 2);
        rs1 += __shfl_xor_sync(0xffffffffu, rs1, 1);
        rs1 += __shfl_xor_sync(0xffffffffu, rs1, 2);
        l0 = l0 * corr0 + rs0;
        l1 = l1 * corr1 + rs1;
        m0 = mn0;
        m1 = mn1;
#pragma unroll
        for (int ni = 0; ni < 8; ni++) {
            oacc[ni][0] *= corr0;
            oacc[ni][1] *= corr0;
            oacc[ni][2] *= corr1;
            oacc[ni][3] *= corr1;
        }

        // ---- P -> smem (split bf16; warp-local rows) ----
#pragma unroll
        for (int ni = 0; ni < 8; ni++) {
            const int cw = ni * 4 + tg;
            uint32_t h0, L0, h1, L1;
            split2(sacc[ni][0], sacc[ni][1], h0, L0);
            split2(sacc[ni][2], sacc[ni][3], h1, L1);
            Ph[(wm + g) * AW + cw] = h0;
            Pl[(wm + g) * AW + cw] = L0;
            Ph[(wm + g + 8) * AW + cw] = h1;
            Pl[(wm + g + 8) * AW + cw] = L1;
        }
        __syncwarp();

        // ---- O += P @ V ----
#pragma unroll
        for (int ch = 0; ch < 4; ch++) {
            const int kw = ch * 8;
            uint32_t ph[4], pl[4];
            ph[0] = Ph[(wm + g) * AW + kw + tg];
            ph[1] = Ph[(wm + g + 8) * AW + kw + tg];
            ph[2] = Ph[(wm + g) * AW + kw + tg + 4];
            ph[3] = Ph[(wm + g + 8) * AW + kw + tg + 4];
            pl[0] = Pl[(wm + g) * AW + kw + tg];
            pl[1] = Pl[(wm + g + 8) * AW + kw + tg];
            pl[2] = Pl[(wm + g) * AW + kw + tg + 4];
            pl[3] = Pl[(wm + g + 8) * AW + kw + tg + 4];
#pragma unroll
            for (int ni = 0; ni < 8; ni++) {
                const int rn = ni * 8 + g;
                uint32_t bh0 = Vh[rn * AW + kw + tg];
                uint32_t bh1 = Vh[rn * AW + kw + tg + 4];
                uint32_t bl0 = Vl[rn * AW + kw + tg];
                uint32_t bl1 = Vl[rn * AW + kw + tg + 4];
                mma_bf16(oacc[ni], ph, bh0, bh1);
                mma_bf16(oacc[ni], pl, bh0, bh1);
                mma_bf16(oacc[ni], ph, bl0, bl1);
            }
        }

        // WAR guard: next iteration's prefetch overwrites buffer cur^1,
        // which other warps may still be reading above.
        __syncthreads();
    }

    // ---- normalize + write split ctx ----
    const float il0 = 1.0f / l0;
    const float il1 = 1.0f / l1;
    uint32_t* ch_w = reinterpret_cast<uint32_t*>(g_ctx_hi);
    uint32_t* cl_w = reinterpret_cast<uint32_t*>(g_ctx_lo);
    const size_t off0 = (((size_t)(b * S_ + gq0)) * (NH_ * D_) + h * D_) >> 1;
    const size_t off1 = (((size_t)(b * S_ + gq1)) * (NH_ * D_) + h * D_) >> 1;
#pragma unroll
    for (int ni = 0; ni < 8; ni++) {
        const int cw = ni * 4 + tg;
        uint32_t h0, L0, h1, L1;
        split2(oacc[ni][0] * il0, oacc[ni][1] * il0, h0, L0);
        split2(oacc[ni][2] * il1, oacc[ni][3] * il1, h1, L1);
        ch_w[off0 + cw] = h0;
        cl_w[off0 + cw] = L0;
        ch_w[off1 + cw] = h1;
        cl_w[off1 + cw] = L1;
    }
}

// ---------------------------------------------------------------------------
// Launch
// ---------------------------------------------------------------------------
extern "C" void kernel_launch(void* const* d_in, const int* in_sizes, int n_in,
                              void* d_out, int out_size) {
    const int*   positions = (const int*)d_in[0];
    const float* hidden    = (const float*)d_in[1];
    const float* Wqkv      = (const float*)d_in[2];
    const float* Wo        = (const float*)d_in[3];
    float* out = (float*)d_out;

    float* qkv_p;
    bf16 *hh, *hl, *wqh, *wql, *woh, *wol, *cth, *ctl;
    cudaGetSymbolAddress((void**)&qkv_p, g_qkv);
    cudaGetSymbolAddress((void**)&hh,  g_hid_hi);
    cudaGetSymbolAddress((void**)&hl,  g_hid_lo);
    cudaGetSymbolAddress((void**)&wqh, g_wqkv_hi);
    cudaGetSymbolAddress((void**)&wql, g_wqkv_lo);
    cudaGetSymbolAddress((void**)&woh, g_wo_hi);
    cudaGetSymbolAddress((void**)&wol, g_wo_lo);
    cudaGetSymbolAddress((void**)&cth, g_ctx_hi);
    cudaGetSymbolAddress((void**)&ctl, g_ctx_lo);

    cudaFuncSetAttribute(gemm_bf16x3, cudaFuncAttributeMaxDynamicSharedMemorySize, GSMEM);
    cudaFuncSetAttribute(attn_kernel, cudaFuncAttributeMaxDynamicSharedMemorySize, ATTN_SMEM);

    // 0. Pre-split operands
    {
        int n2 = B_ * S_ * H_ / 2;
        split_kernel<<<(n2 + 255) / 256, 256>>>(hidden, (uint32_t*)hh, (uint32_t*)hl, n2);
        split_transpose_kernel<<<dim3(QKVF / 32, H_ / 32), dim3(32, 8)>>>(Wqkv, wqh, wql, H_, QKVF);
        split_transpose_kernel<<<dim3(H_ / 32, H_ / 32), dim3(32, 8)>>>(Wo, woh, wol, H_, H_);
    }

    // 1. QKV projection
    gemm_bf16x3<<<dim3(QKVF / 128, (B_ * S_) / 128), 256, GSMEM>>>(
        hh, hl, wqh, wql, qkv_p, B_ * S_, QKVF, H_);

    // 2. RoPE + scatter (split) + V split-transpose
    {
        const int total = B_ * S_ * (NH_ + NKV_) * (D_ / 2);
        rope_scatter_kernel<<<(total + 255) / 256, 256>>>(positions);
        vtranspose_kernel<<<dim3(S_ / 32, NKV_, B_), 256>>>();
    }

    // 3. Causal GQA flash attention (bf16x3 tensor cores)
    attn_kernel<<<dim3(S_ / 64, NH_, B_), 128, ATTN_SMEM>>>(nullptr);

    // 4. Output projection
    gemm_bf16x3<<<dim3(H_ / 128, (B_ * S_) / 128), 256, GSMEM>>>(
        cth, ctl, woh, wol, out, B_ * S_, H_, NH_ * D_);
}

// round 7
// speedup vs baseline: 2.9121x; 1.0942x over previous
#include <cuda_runtime.h>
#include <cuda_bf16.h>
#include <math.h>
#include <stdint.h>

#define B_   2
#define S_   2048
#define H_   2048
#define NH_  32
#define NKV_ 8
#define D_   64
#define QKVF ((NH_ + 2 * NKV_) * D_)   // 3072
#define GQA_ (NH_ / NKV_)              // 4

typedef __nv_bfloat16 bf16;

// ---------------------------------------------------------------------------
// Device scratch
// ---------------------------------------------------------------------------
__device__ float g_qkv[(size_t)B_ * S_ * QKVF];
__device__ bf16 g_hid_hi[(size_t)B_ * S_ * H_];
__device__ bf16 g_hid_lo[(size_t)B_ * S_ * H_];
__device__ bf16 g_wqkv_hi[(size_t)QKVF * H_];   // transposed [N][K]
__device__ bf16 g_wqkv_lo[(size_t)QKVF * H_];
__device__ bf16 g_wo_hi[(size_t)H_ * H_];       // transposed [N][K]
__device__ bf16 g_wo_lo[(size_t)H_ * H_];
__device__ bf16 g_q_hi[(size_t)B_ * NH_ * S_ * D_];
__device__ bf16 g_q_lo[(size_t)B_ * NH_ * S_ * D_];
__device__ bf16 g_k_hi[(size_t)B_ * NKV_ * S_ * D_];
__device__ bf16 g_k_lo[(size_t)B_ * NKV_ * S_ * D_];
__device__ bf16 g_vt_hi[(size_t)B_ * NKV_ * D_ * S_];
__device__ bf16 g_vt_lo[(size_t)B_ * NKV_ * D_ * S_];
__device__ bf16 g_ctx_hi[(size_t)B_ * S_ * NH_ * D_];
__device__ bf16 g_ctx_lo[(size_t)B_ * S_ * NH_ * D_];

// ---------------------------------------------------------------------------
// Helpers
// ---------------------------------------------------------------------------
__device__ __forceinline__ uint32_t smem_u32(const void* p) {
    return (uint32_t)__cvta_generic_to_shared(p);
}
__device__ __forceinline__ void cp_async16_sa(uint32_t sa, const void* g) {
    asm volatile("cp.async.cg.shared.global [%0], [%1], 16;\n" :: "r"(sa), "l"(g));
}
__device__ __forceinline__ void cp_commit() {
    asm volatile("cp.async.commit_group;\n");
}
__device__ __forceinline__ uint32_t pack2(float x, float y) {
    uint32_t r;
    asm("cvt.rn.bf16x2.f32 %0, %1, %2;" : "=r"(r) : "f"(y), "f"(x));
    return r;
}
__device__ __forceinline__ void split2(float x, float y, uint32_t& hi, uint32_t& lo) {
    hi = pack2(x, y);
    float hx = __uint_as_float(hi << 16);
    float hy = __uint_as_float(hi & 0xFFFF0000u);
    lo = pack2(x - hx, y - hy);
}
__device__ __forceinline__ void mma_bf16(float* c, const uint32_t* a,
                                         uint32_t b0, uint32_t b1) {
    asm volatile(
        "mma.sync.aligned.m16n8k16.row.col.f32.bf16.bf16.f32 "
        "{%0,%1,%2,%3},{%4,%5,%6,%7},{%8,%9},{%0,%1,%2,%3};"
        : "+f"(c[0]), "+f"(c[1]), "+f"(c[2]), "+f"(c[3])
        : "r"(a[0]), "r"(a[1]), "r"(a[2]), "r"(a[3]), "r"(b0), "r"(b1));
}
__device__ __forceinline__ void ldsm_x4(uint32_t addr, uint32_t* r) {
    asm volatile("ldmatrix.sync.aligned.m8n8.x4.shared.b16 {%0,%1,%2,%3}, [%4];"
                 : "=r"(r[0]), "=r"(r[1]), "=r"(r[2]), "=r"(r[3]) : "r"(addr));
}

// ---------------------------------------------------------------------------
// Pre-pass kernels
// ---------------------------------------------------------------------------
__global__ void split_kernel(const float* __restrict__ src,
                             uint32_t* __restrict__ hi, uint32_t* __restrict__ lo,
                             int n2) {
    int i = blockIdx.x * blockDim.x + threadIdx.x;
    if (i >= n2) return;
    float2 v = reinterpret_cast<const float2*>(src)[i];
    uint32_t h, l;
    split2(v.x, v.y, h, l);
    hi[i] = h;
    lo[i] = l;
}

__global__ void split_transpose_kernel(const float* __restrict__ src,
                                       bf16* __restrict__ dhi, bf16* __restrict__ dlo,
                                       int K, int N) {
    __shared__ float t[32][33];
    const int n0 = blockIdx.x * 32, k0 = blockIdx.y * 32;
    const int tx = threadIdx.x, ty = threadIdx.y;
#pragma unroll
    for (int r = 0; r < 4; r++)
        t[ty + 8 * r][tx] = src[(size_t)(k0 + ty + 8 * r) * N + n0 + tx];
    __syncthreads();
#pragma unroll
    for (int r = 0; r < 4; r++) {
        float x = t[tx][ty + 8 * r];
        bf16 h = __float2bfloat16(x);
        float hf = __bfloat162float(h);
        size_t off = (size_t)(n0 + ty + 8 * r) * K + k0 + tx;
        dhi[off] = h;
        dlo[off] = __float2bfloat16(x - hf);
    }
}

// ---------------------------------------------------------------------------
// bf16x3 GEMM: C[M,N](fp32) = A[M,K] @ Bt[N,K]^T.
// 128x128x32 block tile, 256 threads (8 warps 4x2), warp tile 32x64.
// 3-stage cp.async pipeline, ldmatrix fragment loads.
// ---------------------------------------------------------------------------
#define PW 20                        // words per 32-bf16 row (16 + 4 pad)
#define TILE_W (128 * PW)            // 2560 words per tile-array
#define GSMEM (3 * 4 * TILE_W * 4)   // 122880 B

__global__ __launch_bounds__(256)
void gemm_bf16x3(const bf16* __restrict__ Ahi, const bf16* __restrict__ Alo,
                 const bf16* __restrict__ Bhi, const bf16* __restrict__ Blo,
                 float* __restrict__ C, int M, int N, int K) {
    extern __shared__ uint32_t sw[];
    const uint32_t sbase = smem_u32(sw);

    const int tid  = threadIdx.x;
    const int wid  = tid >> 5;
    const int lane = tid & 31;
    const int g  = lane >> 2;
    const int tg = lane & 3;
    const int wm = (wid & 3) * 32;
    const int wn = (wid >> 2) * 64;

    const bf16* gptr[4] = {
        Ahi + (size_t)blockIdx.y * 128 * K,
        Alo + (size_t)blockIdx.y * 128 * K,
        Bhi + (size_t)blockIdx.x * 128 * K,
        Blo + (size_t)blockIdx.x * 128 * K
    };

    // ldmatrix per-thread addresses (byte offsets within a tile-array)
    const uint32_t a_off = (uint32_t)(((wm + (lane & 15)) * PW + (lane >> 4) * 4) * 4);
    const uint32_t b_off = (uint32_t)(((wn + ((lane >> 4) << 3) + (lane & 7)) * PW
                                       + ((lane >> 3) & 1) * 4) * 4);

    float acc[2][8][4];
#pragma unroll
    for (int mi = 0; mi < 2; mi++)
#pragma unroll
        for (int ni = 0; ni < 8; ni++)
#pragma unroll
            for (int r = 0; r < 4; r++) acc[mi][ni][r] = 0.f;

#define GEMM_LOAD(st, k0)                                                     \
    {                                                                          \
        uint32_t s0 = sbase + (st) * (4 * TILE_W) * 4;                         \
        _Pragma("unroll")                                                      \
        for (int j = 0; j < 8; j++) {                                          \
            int idx = tid + j * 256;                                           \
            int arr = j >> 1;                                                  \
            int r = (idx >> 2) & 127, c = idx & 3;                             \
            cp_async16_sa(s0 + (arr * TILE_W + r * PW + c * 4) * 4,            \
                          gptr[arr] + (size_t)r * K + (k0) + c * 8);           \
        }                                                                      \
        cp_commit();                                                           \
    }

    const int NIT = K / 32;
    GEMM_LOAD(0, 0);
    GEMM_LOAD(1, 32);

    for (int it = 0; it < NIT; ++it) {
        const int st = it % 3;
        if (it + 1 < NIT) {
            asm volatile("cp.async.wait_group 1;\n" ::: "memory");
        } else {
            asm volatile("cp.async.wait_group 0;\n" ::: "memory");
        }
        __syncthreads();
        if (it + 2 < NIT) GEMM_LOAD((it + 2) % 3, (it + 2) * 32);

        const uint32_t sA_h = sbase + (st * 4 * TILE_W) * 4;
        const uint32_t sA_l = sA_h + TILE_W * 4;
        const uint32_t sB_h = sA_h + 2 * TILE_W * 4;
        const uint32_t sB_l = sA_h + 3 * TILE_W * 4;

#pragma unroll
        for (int ch = 0; ch < 2; ch++) {
            const uint32_t kb = (uint32_t)(ch * 8 * 4);   // kw bytes
            uint32_t ah[2][4], al[2][4];
#pragma unroll
            for (int mi = 0; mi < 2; mi++) {
                ldsm_x4(sA_h + a_off + (uint32_t)(mi * 16 * PW * 4) + kb, ah[mi]);
                ldsm_x4(sA_l + a_off + (uint32_t)(mi * 16 * PW * 4) + kb, al[mi]);
            }
#pragma unroll
            for (int p = 0; p < 4; p++) {
                uint32_t bh[4], bl[4];
                ldsm_x4(sB_h + b_off + (uint32_t)(p * 16 * PW * 4) + kb, bh);
                ldsm_x4(sB_l + b_off + (uint32_t)(p * 16 * PW * 4) + kb, bl);
#pragma unroll
                for (int s = 0; s < 2; s++) {
                    const int ni = 2 * p + s;
#pragma unroll
                    for (int mi = 0; mi < 2; mi++) {
                        mma_bf16(acc[mi][ni], ah[mi], bh[2 * s], bh[2 * s + 1]);
                        mma_bf16(acc[mi][ni], al[mi], bh[2 * s], bh[2 * s + 1]);
                        mma_bf16(acc[mi][ni], ah[mi], bl[2 * s], bl[2 * s + 1]);
                    }
                }
            }
        }
    }

#pragma unroll
    for (int mi = 0; mi < 2; mi++) {
        const int row = blockIdx.y * 128 + wm + mi * 16 + g;
#pragma unroll
        for (int ni = 0; ni < 8; ni++) {
            const int col = blockIdx.x * 128 + wn + ni * 8 + 2 * tg;
            *reinterpret_cast<float2*>(C + (size_t)row * N + col) =
                make_float2(acc[mi][ni][0], acc[mi][ni][1]);
            *reinterpret_cast<float2*>(C + (size_t)(row + 8) * N + col) =
                make_float2(acc[mi][ni][2], acc[mi][ni][3]);
        }
    }
}

// ---------------------------------------------------------------------------
// RoPE + scatter (unchanged)
// ---------------------------------------------------------------------------
__global__ void rope_scatter_kernel(const int* __restrict__ positions) {
    const int total = B_ * S_ * (NH_ + NKV_) * (D_ / 2);
    int idx = blockIdx.x * blockDim.x + threadIdx.x;
    if (idx >= total) return;

    const int d = idx & 31;
    int t = idx >> 5;
    const int h = t % (NH_ + NKV_); t /= (NH_ + NKV_);
    const int s = t % S_;
    const int b = t / S_;

    const float pos = (float)positions[s];
    const float inv = powf(10000.0f, -(float)(2 * d) / (float)D_);
    const float freq = pos * inv;
    const double dr = (double)freq;
    const double kq = floor(dr * 0.15915494309189534 + 0.5);
    const float  rr = (float)(dr - kq * 6.283185307179586477);
    float sn, cs;
    sincosf(rr, &sn, &cs);

    const float* base = g_qkv + (size_t)(b * S_ + s) * QKVF;
    float x0, x1, scale;
    bf16 *dhi, *dlo;
    if (h < NH_) {
        x0 = base[h * D_ + d];
        x1 = base[h * D_ + d + 32];
        size_t off = (((size_t)(b * NH_ + h)) * S_ + s) * D_;
        dhi = g_q_hi + off; dlo = g_q_lo + off;
        scale = 0.125f;
    } else {
        const int hk = h - NH_;
        x0 = base[NH_ * D_ + hk * D_ + d];
        x1 = base[NH_ * D_ + hk * D_ + d + 32];
        size_t off = (((size_t)(b * NKV_ + hk)) * S_ + s) * D_;
        dhi = g_k_hi + off; dlo = g_k_lo + off;
        scale = 1.0f;
    }
    float v0 = (x0 * cs - x1 * sn) * scale;
    float v1 = (x1 * cs + x0 * sn) * scale;
    bf16 h0 = __float2bfloat16(v0);
    bf16 h1 = __float2bfloat16(v1);
    dhi[d]      = h0;
    dhi[d + 32] = h1;
    dlo[d]      = __float2bfloat16(v0 - __bfloat162float(h0));
    dlo[d + 32] = __float2bfloat16(v1 - __bfloat162float(h1));
}

__global__ void vtranspose_kernel() {
    __shared__ float t[32][65];
    const int s0 = blockIdx.x * 32;
    const int kh = blockIdx.y;
    const int b  = blockIdx.z;
    const int tid = threadIdx.x;

    const float* src = g_qkv + (size_t)b * S_ * QKVF + (NH_ + NKV_) * D_ + kh * D_;
#pragma unroll
    for (int j = 0; j < 8; j++) {
        int e = tid + j * 256;
        int s = e >> 6, d = e & 63;
        t[s][d] = src[(size_t)(s0 + s) * QKVF + d];
    }
    __syncthreads();

    bf16* dhi = g_vt_hi + ((size_t)(b * NKV_ + kh)) * D_ * S_;
    bf16* dlo = g_vt_lo + ((size_t)(b * NKV_ + kh)) * D_ * S_;
#pragma unroll
    for (int j = 0; j < 8; j++) {
        int e = tid + j * 256;
        int d = e >> 5, s = e & 31;
        float x = t[s][d];
        bf16 h = __float2bfloat16(x);
        dhi[(size_t)d * S_ + s0 + s] = h;
        dlo[(size_t)d * S_ + s0 + s] = __float2bfloat16(x - __bfloat162float(h));
    }
}

// ---------------------------------------------------------------------------
// bf16x3 causal flash attention with ldmatrix fragment loads.
// Same structure/layout as the R5 passing version.
// ---------------------------------------------------------------------------
#define AW 36
#define AT_W (64 * AW)
#define ATTN_SMEM (12 * AT_W * 4)

__global__ __launch_bounds__(128)
void attn_kernel(float* /*unused*/) {
    extern __shared__ uint32_t sw[];
    const uint32_t sbase = smem_u32(sw);

    const int qtile = gridDim.x - 1 - blockIdx.x;
    const int h = blockIdx.y;
    const int b = blockIdx.z;
    const int kvh = h / GQA_;
    const int q0 = qtile * 64;

    const bf16* qh_g = g_q_hi + (((size_t)(b * NH_ + h)) * S_ + q0) * D_;
    const bf16* ql_g = g_q_lo + (((size_t)(b * NH_ + h)) * S_ + q0) * D_;
    const bf16* kh_g = g_k_hi + ((size_t)(b * NKV_ + kvh)) * S_ * D_;
    const bf16* kl_g = g_k_lo + ((size_t)(b * NKV_ + kvh)) * S_ * D_;
    const bf16* vh_g = g_vt_hi + ((size_t)(b * NKV_ + kvh)) * D_ * S_;
    const bf16* vl_g = g_vt_lo + ((size_t)(b * NKV_ + kvh)) * D_ * S_;

    const int tid  = threadIdx.x;
    const int wid  = tid >> 5;
    const int lane = tid & 31;
    const int g  = lane >> 2;
    const int tg = lane & 3;
    const int wm = wid * 16;

    // ldmatrix per-thread byte offsets within a 64-row tile-array
    const uint32_t aq_off = (uint32_t)(((wm + (lane & 15)) * AW + (lane >> 4) * 4) * 4);
    const uint32_t bk_off = (uint32_t)(((((lane >> 4) << 3) + (lane & 7)) * AW
                                        + ((lane >> 3) & 1) * 4) * 4);

#pragma unroll
    for (int j = 0; j < 8; j++) {
        int idx = tid + j * 128;
        int r = (idx >> 3) & 63, c = idx & 7;
        const bf16* src = (j >> 2) ? ql_g : qh_g;
        cp_async16_sa(sbase + ((j >> 2) * AT_W + r * AW + c * 4) * 4,
                      src + (size_t)r * D_ + c * 8);
    }
    cp_commit();

#define ATTN_LOAD_KV(st, kt)                                                    \
    {                                                                            \
        _Pragma("unroll")                                                        \
        for (int j = 0; j < 16; j++) {                                           \
            int idx = tid + j * 128;                                              \
            int arr = j >> 2;                                                     \
            int r = (idx >> 3) & 63, c = idx & 7;                                 \
            int tile = (arr < 2 ? 4 : 8) + 2 * (st) + (arr & 1);                  \
            const bf16* src;                                                      \
            size_t goff;                                                          \
            if (arr == 0)      { src = kh_g; goff = (size_t)((kt) * 64 + r) * D_ + c * 8; } \
            else if (arr == 1) { src = kl_g; goff = (size_t)((kt) * 64 + r) * D_ + c * 8; } \
            else if (arr == 2) { src = vh_g; goff = (size_t)r * S_ + (kt) * 64 + c * 8; }   \
            else               { src = vl_g; goff = (size_t)r * S_ + (kt) * 64 + c * 8; }   \
            cp_async16_sa(sbase + (tile * AT_W + r * AW + c * 4) * 4, src + goff); \
        }                                                                         \
        cp_commit();                                                              \
    }

    ATTN_LOAD_KV(0, 0);

    float oacc[8][4];
    float m0 = -1e30f, m1 = -1e30f, l0 = 0.f, l1 = 0.f;
#pragma unroll
    for (int ni = 0; ni < 8; ni++)
#pragma unroll
        for (int r = 0; r < 4; r++) oacc[ni][r] = 0.f;

    const int gq0 = q0 + wm + g;
    const int gq1 = gq0 + 8;

    const uint32_t Qh_b = sbase;
    const uint32_t Ql_b = sbase + AT_W * 4;
    uint32_t* Ph = sw + 2 * AT_W;
    uint32_t* Pl = sw + 3 * AT_W;
    const uint32_t Ph_b = sbase + 2 * AT_W * 4;
    const uint32_t Pl_b = sbase + 3 * AT_W * 4;

    for (int kt = 0; kt <= qtile; kt++) {
        const int cur = kt & 1;
        if (kt + 1 <= qtile) {
            ATTN_LOAD_KV(cur ^ 1, kt + 1);
            asm volatile("cp.async.wait_group 1;\n");
        } else {
            asm volatile("cp.async.wait_group 0;\n");
        }
        __syncthreads();

        const uint32_t Kh_b = sbase + (4 + 2 * cur) * AT_W * 4;
        const uint32_t Kl_b = sbase + (5 + 2 * cur) * AT_W * 4;
        const uint32_t Vh_b = sbase + (8 + 2 * cur) * AT_W * 4;
        const uint32_t Vl_b = sbase + (9 + 2 * cur) * AT_W * 4;

        // ---- S = Q @ K^T ----
        float sacc[8][4];
#pragma unroll
        for (int ni = 0; ni < 8; ni++)
#pragma unroll
            for (int r = 0; r < 4; r++) sacc[ni][r] = 0.f;

#pragma unroll
        for (int ch = 0; ch < 4; ch++) {
            const uint32_t kb = (uint32_t)(ch * 8 * 4);
            uint32_t qh[4], ql[4];
            ldsm_x4(Qh_b + aq_off + kb, qh);
            ldsm_x4(Ql_b + aq_off + kb, ql);
#pragma unroll
            for (int p = 0; p < 4; p++) {
                uint32_t kh4[4], kl4[4];
                ldsm_x4(Kh_b + bk_off + (uint32_t)(p * 16 * AW * 4) + kb, kh4);
                ldsm_x4(Kl_b + bk_off + (uint32_t)(p * 16 * AW * 4) + kb, kl4);
#pragma unroll
                for (int s = 0; s < 2; s++) {
                    const int ni = 2 * p + s;
                    mma_bf16(sacc[ni], qh, kh4[2 * s], kh4[2 * s + 1]);
                    mma_bf16(sacc[ni], ql, kh4[2 * s], kh4[2 * s + 1]);
                    mma_bf16(sacc[ni], qh, kl4[2 * s], kl4[2 * s + 1]);
                }
            }
        }

        // ---- causal mask ----
        if (kt == qtile) {
#pragma unroll
            for (int ni = 0; ni < 8; ni++) {
                const int col = kt * 64 + ni * 8 + 2 * tg;
                if (col     > gq0) sacc[ni][0] = -1e30f;
                if (col + 1 > gq0) sacc[ni][1] = -1e30f;
                if (col     > gq1) sacc[ni][2] = -1e30f;
                if (col + 1 > gq1) sacc[ni][3] = -1e30f;
            }
        }

        // ---- online softmax ----
        float mx0 = -1e30f, mx1 = -1e30f;
#pragma unroll
        for (int ni = 0; ni < 8; ni++) {
            mx0 = fmaxf(mx0, fmaxf(sacc[ni][0], sacc[ni][1]));
            mx1 = fmaxf(mx1, fmaxf(sacc[ni][2], sacc[ni][3]));
        }
        mx0 = fmaxf(mx0, __shfl_xor_sync(0xffffffffu, mx0, 1));
        mx0 = fmaxf(mx0, __shfl_xor_sync(0xffffffffu, mx0, 2));
        mx1 = fmaxf(mx1, __shfl_xor_sync(0xffffffffu, mx1, 1));
        mx1 = fmaxf(mx1, __shfl_xor_sync(0xffffffffu, mx1, 2));

        const float mn0 = fmaxf(m0, mx0);
        const float mn1 = fmaxf(m1, mx1);
        const float corr0 = __expf(m0 - mn0);
        const float corr1 = __expf(m1 - mn1);
        float rs0 = 0.f, rs1 = 0.f;
#pragma unroll
        for (int ni = 0; ni < 8; ni++) {
            float p0 = __expf(sacc[ni][0] - mn0);
            float p1 = __expf(sacc[ni][1] - mn0);
            float p2 = __expf(sacc[ni][2] - mn1);
            float p3 = __expf(sacc[ni][3] - mn1);
            sacc[ni][0] = p0; sacc[ni][1] = p1;
            sacc[ni][2] = p2; sacc[ni][3] = p3;
            rs0 += p0 + p1;
            rs1 += p2 + p3;
        }
        rs0 += __shfl_xor_sync(0xffffffffu, rs0, 1);
        rs0 += __shfl_xor_sync(0xffffffffu, rs0, 2);
        rs1 += __shfl_xor_sync(0xffffffffu, rs1, 1);
        rs1 += __shfl_xor_sync(0xffffffffu, rs1, 2);
        l0 = l0 * corr0 + rs0;
        l1 = l1 * corr1 + rs1;
        m0 = mn0;
        m1 = mn1;
#pragma unroll
        for (int ni = 0; ni < 8; ni++) {
            oacc[ni][0] *= corr0;
            oacc[ni][1] *= corr0;
            oacc[ni][2] *= corr1;
            oacc[ni][3] *= corr1;
        }

        // ---- P -> smem (split bf16; warp-local rows) ----
#pragma unroll
        for (int ni = 0; ni < 8; ni++) {
            const int cw = ni * 4 + tg;
            uint32_t h0, L0, h1, L1;
            split2(sacc[ni][0], sacc[ni][1], h0, L0);
            split2(sacc[ni][2], sacc[ni][3], h1, L1);
            Ph[(wm + g) * AW + cw] = h0;
            Pl[(wm + g) * AW + cw] = L0;
            Ph[(wm + g + 8) * AW + cw] = h1;
            Pl[(wm + g + 8) * AW + cw] = L1;
        }
        __syncwarp();

        // ---- O += P @ V ----
#pragma unroll
        for (int ch = 0; ch < 4; ch++) {
            const uint32_t kb = (uint32_t)(ch * 8 * 4);
            uint32_t ph[4], pl[4];
            ldsm_x4(Ph_b + aq_off + kb, ph);
            ldsm_x4(Pl_b + aq_off + kb, pl);
#pragma unroll
            for (int p = 0; p < 4; p++) {
                uint32_t vh4[4], vl4[4];
                ldsm_x4(Vh_b + bk_off + (uint32_t)(p * 16 * AW * 4) + kb, vh4);
                ldsm_x4(Vl_b + bk_off + (uint32_t)(p * 16 * AW * 4) + kb, vl4);
#pragma unroll
                for (int s = 0; s < 2; s++) {
                    const int ni = 2 * p + s;
                    mma_bf16(oacc[ni], ph, vh4[2 * s], vh4[2 * s + 1]);
                    mma_bf16(oacc[ni], pl, vh4[2 * s], vh4[2 * s + 1]);
                    mma_bf16(oacc[ni], ph, vl4[2 * s], vl4[2 * s + 1]);
                }
            }
        }

        // WAR guard before next prefetch overwrites buffer cur^1
        __syncthreads();
    }

    const float il0 = 1.0f / l0;
    const float il1 = 1.0f / l1;
    uint32_t* ch_w = reinterpret_cast<uint32_t*>(g_ctx_hi);
    uint32_t* cl_w = reinterpret_cast<uint32_t*>(g_ctx_lo);
    const size_t off0 = (((size_t)(b * S_ + gq0)) * (NH_ * D_) + h * D_) >> 1;
    const size_t off1 = (((size_t)(b * S_ + gq1)) * (NH_ * D_) + h * D_) >> 1;
#pragma unroll
    for (int ni = 0; ni < 8; ni++) {
        const int cw = ni * 4 + tg;
        uint32_t h0, L0, h1, L1;
        split2(oacc[ni][0] * il0, oacc[ni][1] * il0, h0, L0);
        split2(oacc[ni][2] * il1, oacc[ni][3] * il1, h1, L1);
        ch_w[off0 + cw] = h0;
        cl_w[off0 + cw] = L0;
        ch_w[off1 + cw] = h1;
        cl_w[off1 + cw] = L1;
    }
}

// ---------------------------------------------------------------------------
// Launch
// ---------------------------------------------------------------------------
extern "C" void kernel_launch(void* const* d_in, const int* in_sizes, int n_in,
                              void* d_out, int out_size) {
    const int*   positions = (const int*)d_in[0];
    const float* hidden    = (const float*)d_in[1];
    const float* Wqkv      = (const float*)d_in[2];
    const float* Wo        = (const float*)d_in[3];
    float* out = (float*)d_out;

    float* qkv_p;
    bf16 *hh, *hl, *wqh, *wql, *woh, *wol, *cth, *ctl;
    cudaGetSymbolAddress((void**)&qkv_p, g_qkv);
    cudaGetSymbolAddress((void**)&hh,  g_hid_hi);
    cudaGetSymbolAddress((void**)&hl,  g_hid_lo);
    cudaGetSymbolAddress((void**)&wqh, g_wqkv_hi);
    cudaGetSymbolAddress((void**)&wql, g_wqkv_lo);
    cudaGetSymbolAddress((void**)&woh, g_wo_hi);
    cudaGetSymbolAddress((void**)&wol, g_wo_lo);
    cudaGetSymbolAddress((void**)&cth, g_ctx_hi);
    cudaGetSymbolAddress((void**)&ctl, g_ctx_lo);

    cudaFuncSetAttribute(gemm_bf16x3, cudaFuncAttributeMaxDynamicSharedMemorySize, GSMEM);
    cudaFuncSetAttribute(attn_kernel, cudaFuncAttributeMaxDynamicSharedMemorySize, ATTN_SMEM);

    // 0. Pre-split operands
    {
        int n2 = B_ * S_ * H_ / 2;
        split_kernel<<<(n2 + 255) / 256, 256>>>(hidden, (uint32_t*)hh, (uint32_t*)hl, n2);
        split_transpose_kernel<<<dim3(QKVF / 32, H_ / 32), dim3(32, 8)>>>(Wqkv, wqh, wql, H_, QKVF);
        split_transpose_kernel<<<dim3(H_ / 32, H_ / 32), dim3(32, 8)>>>(Wo, woh, wol, H_, H_);
    }

    // 1. QKV projection
    gemm_bf16x3<<<dim3(QKVF / 128, (B_ * S_) / 128), 256, GSMEM>>>(
        hh, hl, wqh, wql, qkv_p, B_ * S_, QKVF, H_);

    // 2. RoPE + scatter (split) + V split-transpose
    {
        const int total = B_ * S_ * (NH_ + NKV_) * (D_ / 2);
        rope_scatter_kernel<<<(total + 255) / 256, 256>>>(positions);
        vtranspose_kernel<<<dim3(S_ / 32, NKV_, B_), 256>>>();
    }

    // 3. Causal GQA flash attention
    attn_kernel<<<dim3(S_ / 64, NH_, B_), 128, ATTN_SMEM>>>(nullptr);

    // 4. Output projection
    gemm_bf16x3<<<dim3(H_ / 128, (B_ * S_) / 128), 256, GSMEM>>>(
        cth, ctl, woh, wol, out, B_ * S_, H_, NH_ * D_);
}

// round 8
// speedup vs baseline: 3.1824x; 1.0928x over previous
#include <cuda_runtime.h>
#include <cuda_bf16.h>
#include <math.h>
#include <stdint.h>

#define B_   2
#define S_   2048
#define H_   2048
#define NH_  32
#define NKV_ 8
#define D_   64
#define QKVF ((NH_ + 2 * NKV_) * D_)   // 3072
#define GQA_ (NH_ / NKV_)              // 4

typedef __nv_bfloat16 bf16;

// ---------------------------------------------------------------------------
// Device scratch
// ---------------------------------------------------------------------------
__device__ float g_qkv[(size_t)B_ * S_ * QKVF];
__device__ bf16 g_hid_hi[(size_t)B_ * S_ * H_];
__device__ bf16 g_hid_lo[(size_t)B_ * S_ * H_];
__device__ bf16 g_wqkv_hi[(size_t)QKVF * H_];   // transposed [N][K]
__device__ bf16 g_wqkv_lo[(size_t)QKVF * H_];
__device__ bf16 g_wo_hi[(size_t)H_ * H_];       // transposed [N][K]
__device__ bf16 g_wo_lo[(size_t)H_ * H_];
__device__ bf16 g_q_hi[(size_t)B_ * NH_ * S_ * D_];
__device__ bf16 g_q_lo[(size_t)B_ * NH_ * S_ * D_];
__device__ bf16 g_k_hi[(size_t)B_ * NKV_ * S_ * D_];
__device__ bf16 g_k_lo[(size_t)B_ * NKV_ * S_ * D_];
__device__ bf16 g_vt_hi[(size_t)B_ * NKV_ * D_ * S_];
__device__ bf16 g_vt_lo[(size_t)B_ * NKV_ * D_ * S_];
__device__ bf16 g_ctx_hi[(size_t)B_ * S_ * NH_ * D_];
__device__ bf16 g_ctx_lo[(size_t)B_ * S_ * NH_ * D_];

// ---------------------------------------------------------------------------
// Helpers
// ---------------------------------------------------------------------------
__device__ __forceinline__ uint32_t smem_u32(const void* p) {
    return (uint32_t)__cvta_generic_to_shared(p);
}
__device__ __forceinline__ void cp_async16_sa(uint32_t sa, const void* g) {
    asm volatile("cp.async.cg.shared.global [%0], [%1], 16;\n" :: "r"(sa), "l"(g));
}
__device__ __forceinline__ void cp_commit() {
    asm volatile("cp.async.commit_group;\n");
}
__device__ __forceinline__ uint32_t pack2(float x, float y) {
    uint32_t r;
    asm("cvt.rn.bf16x2.f32 %0, %1, %2;" : "=r"(r) : "f"(y), "f"(x));
    return r;
}
__device__ __forceinline__ void split2(float x, float y, uint32_t& hi, uint32_t& lo) {
    hi = pack2(x, y);
    float hx = __uint_as_float(hi << 16);
    float hy = __uint_as_float(hi & 0xFFFF0000u);
    lo = pack2(x - hx, y - hy);
}
__device__ __forceinline__ void mma_bf16(float* c, const uint32_t* a,
                                         uint32_t b0, uint32_t b1) {
    asm volatile(
        "mma.sync.aligned.m16n8k16.row.col.f32.bf16.bf16.f32 "
        "{%0,%1,%2,%3},{%4,%5,%6,%7},{%8,%9},{%0,%1,%2,%3};"
        : "+f"(c[0]), "+f"(c[1]), "+f"(c[2]), "+f"(c[3])
        : "r"(a[0]), "r"(a[1]), "r"(a[2]), "r"(a[3]), "r"(b0), "r"(b1));
}
__device__ __forceinline__ void ldsm_x4(uint32_t addr, uint32_t* r) {
    asm volatile("ldmatrix.sync.aligned.m8n8.x4.shared.b16 {%0,%1,%2,%3}, [%4];"
                 : "=r"(r[0]), "=r"(r[1]), "=r"(r[2]), "=r"(r[3]) : "r"(addr));
}

// ---------------------------------------------------------------------------
// Pre-pass kernels
// ---------------------------------------------------------------------------
__global__ void split_kernel(const float* __restrict__ src,
                             uint32_t* __restrict__ hi, uint32_t* __restrict__ lo,
                             int n2) {
    int i = blockIdx.x * blockDim.x + threadIdx.x;
    if (i >= n2) return;
    float2 v = reinterpret_cast<const float2*>(src)[i];
    uint32_t h, l;
    split2(v.x, v.y, h, l);
    hi[i] = h;
    lo[i] = l;
}

__global__ void split_transpose_kernel(const float* __restrict__ src,
                                       bf16* __restrict__ dhi, bf16* __restrict__ dlo,
                                       int K, int N) {
    __shared__ float t[32][33];
    const int n0 = blockIdx.x * 32, k0 = blockIdx.y * 32;
    const int tx = threadIdx.x, ty = threadIdx.y;
#pragma unroll
    for (int r = 0; r < 4; r++)
        t[ty + 8 * r][tx] = src[(size_t)(k0 + ty + 8 * r) * N + n0 + tx];
    __syncthreads();
#pragma unroll
    for (int r = 0; r < 4; r++) {
        float x = t[tx][ty + 8 * r];
        bf16 h = __float2bfloat16(x);
        float hf = __bfloat162float(h);
        size_t off = (size_t)(n0 + ty + 8 * r) * K + k0 + tx;
        dhi[off] = h;
        dlo[off] = __float2bfloat16(x - hf);
    }
}

// ---------------------------------------------------------------------------
// bf16x3 GEMM: C[M,N](fp32) = A[M,K] @ Bt[N,K]^T.
// 128x128x32 block tile, 256 threads (8 warps 4x2), warp tile 32x64.
// 2-stage cp.async pipeline, ldmatrix loads, 2 CTAs/SM (reg cap 128).
// ---------------------------------------------------------------------------
#define PW 20                        // words per 32-bf16 row (16 + 4 pad)
#define TILE_W (128 * PW)            // 2560 words per tile-array
#define GSMEM (2 * 4 * TILE_W * 4)   // 81920 B

__global__ __launch_bounds__(256, 2)
void gemm_bf16x3(const bf16* __restrict__ Ahi, const bf16* __restrict__ Alo,
                 const bf16* __restrict__ Bhi, const bf16* __restrict__ Blo,
                 float* __restrict__ C, int M, int N, int K) {
    extern __shared__ uint32_t sw[];
    const uint32_t sbase = smem_u32(sw);

    const int tid  = threadIdx.x;
    const int wid  = tid >> 5;
    const int lane = tid & 31;
    const int g  = lane >> 2;
    const int tg = lane & 3;
    const int wm = (wid & 3) * 32;
    const int wn = (wid >> 2) * 64;

    const bf16* gptr[4] = {
        Ahi + (size_t)blockIdx.y * 128 * K,
        Alo + (size_t)blockIdx.y * 128 * K,
        Bhi + (size_t)blockIdx.x * 128 * K,
        Blo + (size_t)blockIdx.x * 128 * K
    };

    const uint32_t a_off = (uint32_t)(((wm + (lane & 15)) * PW + (lane >> 4) * 4) * 4);
    const uint32_t b_off = (uint32_t)(((wn + ((lane >> 4) << 3) + (lane & 7)) * PW
                                       + ((lane >> 3) & 1) * 4) * 4);

    float acc[2][8][4];
#pragma unroll
    for (int mi = 0; mi < 2; mi++)
#pragma unroll
        for (int ni = 0; ni < 8; ni++)
#pragma unroll
            for (int r = 0; r < 4; r++) acc[mi][ni][r] = 0.f;

#define GEMM_LOAD(st, k0)                                                     \
    {                                                                          \
        uint32_t s0 = sbase + (st) * (4 * TILE_W) * 4;                         \
        _Pragma("unroll")                                                      \
        for (int j = 0; j < 8; j++) {                                          \
            int idx = tid + j * 256;                                           \
            int arr = j >> 1;                                                  \
            int r = (idx >> 2) & 127, c = idx & 3;                             \
            cp_async16_sa(s0 + (arr * TILE_W + r * PW + c * 4) * 4,            \
                          gptr[arr] + (size_t)r * K + (k0) + c * 8);           \
        }                                                                      \
        cp_commit();                                                           \
    }

    const int NIT = K / 32;
    GEMM_LOAD(0, 0);

    for (int it = 0; it < NIT; ++it) {
        const int st = it & 1;
        if (it + 1 < NIT) {
            GEMM_LOAD(st ^ 1, (it + 1) * 32);
            asm volatile("cp.async.wait_group 1;\n" ::: "memory");
        } else {
            asm volatile("cp.async.wait_group 0;\n" ::: "memory");
        }
        __syncthreads();

        const uint32_t sA_h = sbase + (st * 4 * TILE_W) * 4;
        const uint32_t sA_l = sA_h + TILE_W * 4;
        const uint32_t sB_h = sA_h + 2 * TILE_W * 4;
        const uint32_t sB_l = sA_h + 3 * TILE_W * 4;

#pragma unroll
        for (int ch = 0; ch < 2; ch++) {
            const uint32_t kb = (uint32_t)(ch * 8 * 4);
            uint32_t ah[2][4], al[2][4];
#pragma unroll
            for (int mi = 0; mi < 2; mi++) {
                ldsm_x4(sA_h + a_off + (uint32_t)(mi * 16 * PW * 4) + kb, ah[mi]);
                ldsm_x4(sA_l + a_off + (uint32_t)(mi * 16 * PW * 4) + kb, al[mi]);
            }
#pragma unroll
            for (int p = 0; p < 4; p++) {
                uint32_t bh[4], bl[4];
                ldsm_x4(sB_h + b_off + (uint32_t)(p * 16 * PW * 4) + kb, bh);
                ldsm_x4(sB_l + b_off + (uint32_t)(p * 16 * PW * 4) + kb, bl);
#pragma unroll
                for (int s = 0; s < 2; s++) {
                    const int ni = 2 * p + s;
#pragma unroll
                    for (int mi = 0; mi < 2; mi++) {
                        mma_bf16(acc[mi][ni], ah[mi], bh[2 * s], bh[2 * s + 1]);
                        mma_bf16(acc[mi][ni], al[mi], bh[2 * s], bh[2 * s + 1]);
                        mma_bf16(acc[mi][ni], ah[mi], bl[2 * s], bl[2 * s + 1]);
                    }
                }
            }
        }
        __syncthreads();
    }

#pragma unroll
    for (int mi = 0; mi < 2; mi++) {
        const int row = blockIdx.y * 128 + wm + mi * 16 + g;
#pragma unroll
        for (int ni = 0; ni < 8; ni++) {
            const int col = blockIdx.x * 128 + wn + ni * 8 + 2 * tg;
            *reinterpret_cast<float2*>(C + (size_t)row * N + col) =
                make_float2(acc[mi][ni][0], acc[mi][ni][1]);
            *reinterpret_cast<float2*>(C + (size_t)(row + 8) * N + col) =
                make_float2(acc[mi][ni][2], acc[mi][ni][3]);
        }
    }
}

// ---------------------------------------------------------------------------
// RoPE + scatter (unchanged)
// ---------------------------------------------------------------------------
__global__ void rope_scatter_kernel(const int* __restrict__ positions) {
    const int total = B_ * S_ * (NH_ + NKV_) * (D_ / 2);
    int idx = blockIdx.x * blockDim.x + threadIdx.x;
    if (idx >= total) return;

    const int d = idx & 31;
    int t = idx >> 5;
    const int h = t % (NH_ + NKV_); t /= (NH_ + NKV_);
    const int s = t % S_;
    const int b = t / S_;

    const float pos = (float)positions[s];
    const float inv = powf(10000.0f, -(float)(2 * d) / (float)D_);
    const float freq = pos * inv;
    const double dr = (double)freq;
    const double kq = floor(dr * 0.15915494309189534 + 0.5);
    const float  rr = (float)(dr - kq * 6.283185307179586477);
    float sn, cs;
    sincosf(rr, &sn, &cs);

    const float* base = g_qkv + (size_t)(b * S_ + s) * QKVF;
    float x0, x1, scale;
    bf16 *dhi, *dlo;
    if (h < NH_) {
        x0 = base[h * D_ + d];
        x1 = base[h * D_ + d + 32];
        size_t off = (((size_t)(b * NH_ + h)) * S_ + s) * D_;
        dhi = g_q_hi + off; dlo = g_q_lo + off;
        scale = 0.125f;
    } else {
        const int hk = h - NH_;
        x0 = base[NH_ * D_ + hk * D_ + d];
        x1 = base[NH_ * D_ + hk * D_ + d + 32];
        size_t off = (((size_t)(b * NKV_ + hk)) * S_ + s) * D_;
        dhi = g_k_hi + off; dlo = g_k_lo + off;
        scale = 1.0f;
    }
    float v0 = (x0 * cs - x1 * sn) * scale;
    float v1 = (x1 * cs + x0 * sn) * scale;
    bf16 h0 = __float2bfloat16(v0);
    bf16 h1 = __float2bfloat16(v1);
    dhi[d]      = h0;
    dhi[d + 32] = h1;
    dlo[d]      = __float2bfloat16(v0 - __bfloat162float(h0));
    dlo[d + 32] = __float2bfloat16(v1 - __bfloat162float(h1));
}

__global__ void vtranspose_kernel() {
    __shared__ float t[32][65];
    const int s0 = blockIdx.x * 32;
    const int kh = blockIdx.y;
    const int b  = blockIdx.z;
    const int tid = threadIdx.x;

    const float* src = g_qkv + (size_t)b * S_ * QKVF + (NH_ + NKV_) * D_ + kh * D_;
#pragma unroll
    for (int j = 0; j < 8; j++) {
        int e = tid + j * 256;
        int s = e >> 6, d = e & 63;
        t[s][d] = src[(size_t)(s0 + s) * QKVF + d];
    }
    __syncthreads();

    bf16* dhi = g_vt_hi + ((size_t)(b * NKV_ + kh)) * D_ * S_;
    bf16* dlo = g_vt_lo + ((size_t)(b * NKV_ + kh)) * D_ * S_;
#pragma unroll
    for (int j = 0; j < 8; j++) {
        int e = tid + j * 256;
        int d = e >> 5, s = e & 31;
        float x = t[s][d];
        bf16 h = __float2bfloat16(x);
        dhi[(size_t)d * S_ + s0 + s] = h;
        dlo[(size_t)d * S_ + s0 + s] = __float2bfloat16(x - __bfloat162float(h));
    }
}

// ---------------------------------------------------------------------------
// bf16x3 causal flash attention with ldmatrix loads (R7 passing version).
// ---------------------------------------------------------------------------
#define AW 36
#define AT_W (64 * AW)
#define ATTN_SMEM (12 * AT_W * 4)

__global__ __launch_bounds__(128, 2)
void attn_kernel(float* /*unused*/) {
    extern __shared__ uint32_t sw[];
    const uint32_t sbase = smem_u32(sw);

    const int qtile = gridDim.x - 1 - blockIdx.x;
    const int h = blockIdx.y;
    const int b = blockIdx.z;
    const int kvh = h / GQA_;
    const int q0 = qtile * 64;

    const bf16* qh_g = g_q_hi + (((size_t)(b * NH_ + h)) * S_ + q0) * D_;
    const bf16* ql_g = g_q_lo + (((size_t)(b * NH_ + h)) * S_ + q0) * D_;
    const bf16* kh_g = g_k_hi + ((size_t)(b * NKV_ + kvh)) * S_ * D_;
    const bf16* kl_g = g_k_lo + ((size_t)(b * NKV_ + kvh)) * S_ * D_;
    const bf16* vh_g = g_vt_hi + ((size_t)(b * NKV_ + kvh)) * D_ * S_;
    const bf16* vl_g = g_vt_lo + ((size_t)(b * NKV_ + kvh)) * D_ * S_;

    const int tid  = threadIdx.x;
    const int wid  = tid >> 5;
    const int lane = tid & 31;
    const int g  = lane >> 2;
    const int tg = lane & 3;
    const int wm = wid * 16;

    const uint32_t aq_off = (uint32_t)(((wm + (lane & 15)) * AW + (lane >> 4) * 4) * 4);
    const uint32_t bk_off = (uint32_t)(((((lane >> 4) << 3) + (lane & 7)) * AW
                                        + ((lane >> 3) & 1) * 4) * 4);

#pragma unroll
    for (int j = 0; j < 8; j++) {
        int idx = tid + j * 128;
        int r = (idx >> 3) & 63, c = idx & 7;
        const bf16* src = (j >> 2) ? ql_g : qh_g;
        cp_async16_sa(sbase + ((j >> 2) * AT_W + r * AW + c * 4) * 4,
                      src + (size_t)r * D_ + c * 8);
    }
    cp_commit();

#define ATTN_LOAD_KV(st, kt)                                                    \
    {                                                                            \
        _Pragma("unroll")                                                        \
        for (int j = 0; j < 16; j++) {                                           \
            int idx = tid + j * 128;                                              \
            int arr = j >> 2;                                                     \
            int r = (idx >> 3) & 63, c = idx & 7;                                 \
            int tile = (arr < 2 ? 4 : 8) + 2 * (st) + (arr & 1);                  \
            const bf16* src;                                                      \
            size_t goff;                                                          \
            if (arr == 0)      { src = kh_g; goff = (size_t)((kt) * 64 + r) * D_ + c * 8; } \
            else if (arr == 1) { src = kl_g; goff = (size_t)((kt) * 64 + r) * D_ + c * 8; } \
            else if (arr == 2) { src = vh_g; goff = (size_t)r * S_ + (kt) * 64 + c * 8; }   \
            else               { src = vl_g; goff = (size_t)r * S_ + (kt) * 64 + c * 8; }   \
            cp_async16_sa(sbase + (tile * AT_W + r * AW + c * 4) * 4, src + goff); \
        }                                                                         \
        cp_commit();                                                              \
    }

    ATTN_LOAD_KV(0, 0);

    float oacc[8][4];
    float m0 = -1e30f, m1 = -1e30f, l0 = 0.f, l1 = 0.f;
#pragma unroll
    for (int ni = 0; ni < 8; ni++)
#pragma unroll
        for (int r = 0; r < 4; r++) oacc[ni][r] = 0.f;

    const int gq0 = q0 + wm + g;
    const int gq1 = gq0 + 8;

    const uint32_t Qh_b = sbase;
    const uint32_t Ql_b = sbase + AT_W * 4;
    uint32_t* Ph = sw + 2 * AT_W;
    uint32_t* Pl = sw + 3 * AT_W;
    const uint32_t Ph_b = sbase + 2 * AT_W * 4;
    const uint32_t Pl_b = sbase + 3 * AT_W * 4;

    for (int kt = 0; kt <= qtile; kt++) {
        const int cur = kt & 1;
        if (kt + 1 <= qtile) {
            ATTN_LOAD_KV(cur ^ 1, kt + 1);
            asm volatile("cp.async.wait_group 1;\n");
        } else {
            asm volatile("cp.async.wait_group 0;\n");
        }
        __syncthreads();

        const uint32_t Kh_b = sbase + (4 + 2 * cur) * AT_W * 4;
        const uint32_t Kl_b = sbase + (5 + 2 * cur) * AT_W * 4;
        const uint32_t Vh_b = sbase + (8 + 2 * cur) * AT_W * 4;
        const uint32_t Vl_b = sbase + (9 + 2 * cur) * AT_W * 4;

        float sacc[8][4];
#pragma unroll
        for (int ni = 0; ni < 8; ni++)
#pragma unroll
            for (int r = 0; r < 4; r++) sacc[ni][r] = 0.f;

#pragma unroll
        for (int ch = 0; ch < 4; ch++) {
            const uint32_t kb = (uint32_t)(ch * 8 * 4);
            uint32_t qh[4], ql[4];
            ldsm_x4(Qh_b + aq_off + kb, qh);
            ldsm_x4(Ql_b + aq_off + kb, ql);
#pragma unroll
            for (int p = 0; p < 4; p++) {
                uint32_t kh4[4], kl4[4];
                ldsm_x4(Kh_b + bk_off + (uint32_t)(p * 16 * AW * 4) + kb, kh4);
                ldsm_x4(Kl_b + bk_off + (uint32_t)(p * 16 * AW * 4) + kb, kl4);
#pragma unroll
                for (int s = 0; s < 2; s++) {
                    const int ni = 2 * p + s;
                    mma_bf16(sacc[ni], qh, kh4[2 * s], kh4[2 * s + 1]);
                    mma_bf16(sacc[ni], ql, kh4[2 * s], kh4[2 * s + 1]);
                    mma_bf16(sacc[ni], qh, kl4[2 * s], kl4[2 * s + 1]);
                }
            }
        }

        if (kt == qtile) {
#pragma unroll
            for (int ni = 0; ni < 8; ni++) {
                const int col = kt * 64 + ni * 8 + 2 * tg;
                if (col     > gq0) sacc[ni][0] = -1e30f;
                if (col + 1 > gq0) sacc[ni][1] = -1e30f;
                if (col     > gq1) sacc[ni][2] = -1e30f;
                if (col + 1 > gq1) sacc[ni][3] = -1e30f;
            }
        }

        float mx0 = -1e30f, mx1 = -1e30f;
#pragma unroll
        for (int ni = 0; ni < 8; ni++) {
            mx0 = fmaxf(mx0, fmaxf(sacc[ni][0], sacc[ni][1]));
            mx1 = fmaxf(mx1, fmaxf(sacc[ni][2], sacc[ni][3]));
        }
        mx0 = fmaxf(mx0, __shfl_xor_sync(0xffffffffu, mx0, 1));
        mx0 = fmaxf(mx0, __shfl_xor_sync(0xffffffffu, mx0, 2));
        mx1 = fmaxf(mx1, __shfl_xor_sync(0xffffffffu, mx1, 1));
        mx1 = fmaxf(mx1, __shfl_xor_sync(0xffffffffu, mx1, 2));

        const float mn0 = fmaxf(m0, mx0);
        const float mn1 = fmaxf(m1, mx1);
        const float corr0 = __expf(m0 - mn0);
        const float corr1 = __expf(m1 - mn1);
        float rs0 = 0.f, rs1 = 0.f;
#pragma unroll
        for (int ni = 0; ni < 8; ni++) {
            float p0 = __expf(sacc[ni][0] - mn0);
            float p1 = __expf(sacc[ni][1] - mn0);
            float p2 = __expf(sacc[ni][2] - mn1);
            float p3 = __expf(sacc[ni][3] - mn1);
            sacc[ni][0] = p0; sacc[ni][1] = p1;
            sacc[ni][2] = p2; sacc[ni][3] = p3;
            rs0 += p0 + p1;
            rs1 += p2 + p3;
        }
        rs0 += __shfl_xor_sync(0xffffffffu, rs0, 1);
        rs0 += __shfl_xor_sync(0xffffffffu, rs0, 2);
        rs1 += __shfl_xor_sync(0xffffffffu, rs1, 1);
        rs1 += __shfl_xor_sync(0xffffffffu, rs1, 2);
        l0 = l0 * corr0 + rs0;
        l1 = l1 * corr1 + rs1;
        m0 = mn0;
        m1 = mn1;
#pragma unroll
        for (int ni = 0; ni < 8; ni++) {
            oacc[ni][0] *= corr0;
            oacc[ni][1] *= corr0;
            oacc[ni][2] *= corr1;
            oacc[ni][3] *= corr1;
        }

#pragma unroll
        for (int ni = 0; ni < 8; ni++) {
            const int cw = ni * 4 + tg;
            uint32_t h0, L0, h1, L1;
            split2(sacc[ni][0], sacc[ni][1], h0, L0);
            split2(sacc[ni][2], sacc[ni][3], h1, L1);
            Ph[(wm + g) * AW + cw] = h0;
            Pl[(wm + g) * AW + cw] = L0;
            Ph[(wm + g + 8) * AW + cw] = h1;
            Pl[(wm + g + 8) * AW + cw] = L1;
        }
        __syncwarp();

#pragma unroll
        for (int ch = 0; ch < 4; ch++) {
            const uint32_t kb = (uint32_t)(ch * 8 * 4);
            uint32_t ph[4], pl[4];
            ldsm_x4(Ph_b + aq_off + kb, ph);
            ldsm_x4(Pl_b + aq_off + kb, pl);
#pragma unroll
            for (int p = 0; p < 4; p++) {
                uint32_t vh4[4], vl4[4];
                ldsm_x4(Vh_b + bk_off + (uint32_t)(p * 16 * AW * 4) + kb, vh4);
                ldsm_x4(Vl_b + bk_off + (uint32_t)(p * 16 * AW * 4) + kb, vl4);
#pragma unroll
                for (int s = 0; s < 2; s++) {
                    const int ni = 2 * p + s;
                    mma_bf16(oacc[ni], ph, vh4[2 * s], vh4[2 * s + 1]);
                    mma_bf16(oacc[ni], pl, vh4[2 * s], vh4[2 * s + 1]);
                    mma_bf16(oacc[ni], ph, vl4[2 * s], vl4[2 * s + 1]);
                }
            }
        }

        __syncthreads();
    }

    const float il0 = 1.0f / l0;
    const float il1 = 1.0f / l1;
    uint32_t* ch_w = reinterpret_cast<uint32_t*>(g_ctx_hi);
    uint32_t* cl_w = reinterpret_cast<uint32_t*>(g_ctx_lo);
    const size_t off0 = (((size_t)(b * S_ + gq0)) * (NH_ * D_) + h * D_) >> 1;
    const size_t off1 = (((size_t)(b * S_ + gq1)) * (NH_ * D_) + h * D_) >> 1;
#pragma unroll
    for (int ni = 0; ni < 8; ni++) {
        const int cw = ni * 4 + tg;
        uint32_t h0, L0, h1, L1;
        split2(oacc[ni][0] * il0, oacc[ni][1] * il0, h0, L0);
        split2(oacc[ni][2] * il1, oacc[ni][3] * il1, h1, L1);
        ch_w[off0 + cw] = h0;
        cl_w[off0 + cw] = L0;
        ch_w[off1 + cw] = h1;
        cl_w[off1 + cw] = L1;
    }
}

// ---------------------------------------------------------------------------
// Launch
// ---------------------------------------------------------------------------
extern "C" void kernel_launch(void* const* d_in, const int* in_sizes, int n_in,
                              void* d_out, int out_size) {
    const int*   positions = (const int*)d_in[0];
    const float* hidden    = (const float*)d_in[1];
    const float* Wqkv      = (const float*)d_in[2];
    const float* Wo        = (const float*)d_in[3];
    float* out = (float*)d_out;

    float* qkv_p;
    bf16 *hh, *hl, *wqh, *wql, *woh, *wol, *cth, *ctl;
    cudaGetSymbolAddress((void**)&qkv_p, g_qkv);
    cudaGetSymbolAddress((void**)&hh,  g_hid_hi);
    cudaGetSymbolAddress((void**)&hl,  g_hid_lo);
    cudaGetSymbolAddress((void**)&wqh, g_wqkv_hi);
    cudaGetSymbolAddress((void**)&wql, g_wqkv_lo);
    cudaGetSymbolAddress((void**)&woh, g_wo_hi);
    cudaGetSymbolAddress((void**)&wol, g_wo_lo);
    cudaGetSymbolAddress((void**)&cth, g_ctx_hi);
    cudaGetSymbolAddress((void**)&ctl, g_ctx_lo);

    // Opt into the full 228KB shared carveout so TWO CTAs fit per SM.
    cudaFuncSetAttribute(gemm_bf16x3, cudaFuncAttributeMaxDynamicSharedMemorySize, GSMEM);
    cudaFuncSetAttribute(gemm_bf16x3, cudaFuncAttributePreferredSharedMemoryCarveout, 100);
    cudaFuncSetAttribute(attn_kernel, cudaFuncAttributeMaxDynamicSharedMemorySize, ATTN_SMEM);
    cudaFuncSetAttribute(attn_kernel, cudaFuncAttributePreferredSharedMemoryCarveout, 100);

    // 0. Pre-split operands
    {
        int n2 = B_ * S_ * H_ / 2;
        split_kernel<<<(n2 + 255) / 256, 256>>>(hidden, (uint32_t*)hh, (uint32_t*)hl, n2);
        split_transpose_kernel<<<dim3(QKVF / 32, H_ / 32), dim3(32, 8)>>>(Wqkv, wqh, wql, H_, QKVF);
        split_transpose_kernel<<<dim3(H_ / 32, H_ / 32), dim3(32, 8)>>>(Wo, woh, wol, H_, H_);
    }

    // 1. QKV projection
    gemm_bf16x3<<<dim3(QKVF / 128, (B_ * S_) / 128), 256, GSMEM>>>(
        hh, hl, wqh, wql, qkv_p, B_ * S_, QKVF, H_);

    // 2. RoPE + scatter (split) + V split-transpose
    {
        const int total = B_ * S_ * (NH_ + NKV_) * (D_ / 2);
        rope_scatter_kernel<<<(total + 255) / 256, 256>>>(positions);
        vtranspose_kernel<<<dim3(S_ / 32, NKV_, B_), 256>>>();
    }

    // 3. Causal GQA flash attention
    attn_kernel<<<dim3(S_ / 64, NH_, B_), 128, ATTN_SMEM>>>(nullptr);

    // 4. Output projection
    gemm_bf16x3<<<dim3(H_ / 128, (B_ * S_) / 128), 256, GSMEM>>>(
        cth, ctl, woh, wol, out, B_ * S_, H_, NH_ * D_);
}

// round 9
// speedup vs baseline: 3.2769x; 1.0297x over previous
#include <cuda_runtime.h>
#include <cuda_bf16.h>
#include <math.h>
#include <stdint.h>

#define B_   2
#define S_   2048
#define H_   2048
#define NH_  32
#define NKV_ 8
#define D_   64
#define QKVF ((NH_ + 2 * NKV_) * D_)   // 3072
#define GQA_ (NH_ / NKV_)              // 4

typedef __nv_bfloat16 bf16;

// ---------------------------------------------------------------------------
// Device scratch
// ---------------------------------------------------------------------------
__device__ float g_qkv[(size_t)B_ * S_ * QKVF];
__device__ bf16 g_hid_hi[(size_t)B_ * S_ * H_];
__device__ bf16 g_hid_lo[(size_t)B_ * S_ * H_];
__device__ bf16 g_wqkv_hi[(size_t)QKVF * H_];   // transposed [N][K]
__device__ bf16 g_wqkv_lo[(size_t)QKVF * H_];
__device__ bf16 g_wo_hi[(size_t)H_ * H_];       // transposed [N][K]
__device__ bf16 g_wo_lo[(size_t)H_ * H_];
__device__ bf16 g_q_hi[(size_t)B_ * NH_ * S_ * D_];
__device__ bf16 g_q_lo[(size_t)B_ * NH_ * S_ * D_];
__device__ bf16 g_k_hi[(size_t)B_ * NKV_ * S_ * D_];
__device__ bf16 g_k_lo[(size_t)B_ * NKV_ * S_ * D_];
__device__ bf16 g_vt_hi[(size_t)B_ * NKV_ * D_ * S_];
__device__ bf16 g_vt_lo[(size_t)B_ * NKV_ * D_ * S_];
__device__ bf16 g_ctx_hi[(size_t)B_ * S_ * NH_ * D_];
__device__ bf16 g_ctx_lo[(size_t)B_ * S_ * NH_ * D_];

// ---------------------------------------------------------------------------
// Helpers
// ---------------------------------------------------------------------------
__device__ __forceinline__ uint32_t smem_u32(const void* p) {
    return (uint32_t)__cvta_generic_to_shared(p);
}
__device__ __forceinline__ void cp_async16_sa(uint32_t sa, const void* g) {
    asm volatile("cp.async.cg.shared.global [%0], [%1], 16;\n" :: "r"(sa), "l"(g));
}
__device__ __forceinline__ void cp_commit() {
    asm volatile("cp.async.commit_group;\n");
}
__device__ __forceinline__ uint32_t pack2(float x, float y) {
    uint32_t r;
    asm("cvt.rn.bf16x2.f32 %0, %1, %2;" : "=r"(r) : "f"(y), "f"(x));
    return r;
}
__device__ __forceinline__ void split2(float x, float y, uint32_t& hi, uint32_t& lo) {
    hi = pack2(x, y);
    float hx = __uint_as_float(hi << 16);
    float hy = __uint_as_float(hi & 0xFFFF0000u);
    lo = pack2(x - hx, y - hy);
}
__device__ __forceinline__ void mma_bf16(float* c, const uint32_t* a,
                                         uint32_t b0, uint32_t b1) {
    asm volatile(
        "mma.sync.aligned.m16n8k16.row.col.f32.bf16.bf16.f32 "
        "{%0,%1,%2,%3},{%4,%5,%6,%7},{%8,%9},{%0,%1,%2,%3};"
        : "+f"(c[0]), "+f"(c[1]), "+f"(c[2]), "+f"(c[3])
        : "r"(a[0]), "r"(a[1]), "r"(a[2]), "r"(a[3]), "r"(b0), "r"(b1));
}
__device__ __forceinline__ void ldsm_x4(uint32_t addr, uint32_t* r) {
    asm volatile("ldmatrix.sync.aligned.m8n8.x4.shared.b16 {%0,%1,%2,%3}, [%4];"
                 : "=r"(r[0]), "=r"(r[1]), "=r"(r[2]), "=r"(r[3]) : "r"(addr));
}

// ---------------------------------------------------------------------------
// Pre-pass kernels
// ---------------------------------------------------------------------------
__global__ void split_kernel(const float* __restrict__ src,
                             uint2* __restrict__ hi, uint2* __restrict__ lo,
                             int n4) {
    int i = blockIdx.x * blockDim.x + threadIdx.x;
    if (i >= n4) return;
    float4 v = reinterpret_cast<const float4*>(src)[i];
    uint32_t h0, l0, h1, l1;
    split2(v.x, v.y, h0, l0);
    split2(v.z, v.w, h1, l1);
    hi[i] = make_uint2(h0, h1);
    lo[i] = make_uint2(l0, l1);
}

__global__ void split_transpose_kernel(const float* __restrict__ src,
                                       bf16* __restrict__ dhi, bf16* __restrict__ dlo,
                                       int K, int N) {
    __shared__ float t[32][33];
    const int n0 = blockIdx.x * 32, k0 = blockIdx.y * 32;
    const int tx = threadIdx.x, ty = threadIdx.y;
#pragma unroll
    for (int r = 0; r < 4; r++)
        t[ty + 8 * r][tx] = src[(size_t)(k0 + ty + 8 * r) * N + n0 + tx];
    __syncthreads();
#pragma unroll
    for (int r = 0; r < 4; r++) {
        float x = t[tx][ty + 8 * r];
        bf16 h = __float2bfloat16(x);
        float hf = __bfloat162float(h);
        size_t off = (size_t)(n0 + ty + 8 * r) * K + k0 + tx;
        dhi[off] = h;
        dlo[off] = __float2bfloat16(x - hf);
    }
}

// ---------------------------------------------------------------------------
// bf16x3 GEMM: C[M,N](fp32) = A[M,K] @ Bt[N,K]^T.
// 128x128x32 block tile, 256 threads (8 warps 4x2), warp tile 32x64.
// 2-stage cp.async, ldmatrix loads, 2 CTAs/SM, ONE barrier per iteration.
// ---------------------------------------------------------------------------
#define PW 20                        // words per 32-bf16 row (16 + 4 pad)
#define TILE_W (128 * PW)            // 2560 words per tile-array
#define GSMEM (2 * 4 * TILE_W * 4)   // 81920 B

__global__ __launch_bounds__(256, 2)
void gemm_bf16x3(const bf16* __restrict__ Ahi, const bf16* __restrict__ Alo,
                 const bf16* __restrict__ Bhi, const bf16* __restrict__ Blo,
                 float* __restrict__ C, int M, int N, int K) {
    extern __shared__ uint32_t sw[];
    const uint32_t sbase = smem_u32(sw);

    const int tid  = threadIdx.x;
    const int wid  = tid >> 5;
    const int lane = tid & 31;
    const int g  = lane >> 2;
    const int tg = lane & 3;
    const int wm = (wid & 3) * 32;
    const int wn = (wid >> 2) * 64;

    const bf16* gptr[4] = {
        Ahi + (size_t)blockIdx.y * 128 * K,
        Alo + (size_t)blockIdx.y * 128 * K,
        Bhi + (size_t)blockIdx.x * 128 * K,
        Blo + (size_t)blockIdx.x * 128 * K
    };

    const uint32_t a_off = (uint32_t)(((wm + (lane & 15)) * PW + (lane >> 4) * 4) * 4);
    const uint32_t b_off = (uint32_t)(((wn + ((lane >> 4) << 3) + (lane & 7)) * PW
                                       + ((lane >> 3) & 1) * 4) * 4);

    float acc[2][8][4];
#pragma unroll
    for (int mi = 0; mi < 2; mi++)
#pragma unroll
        for (int ni = 0; ni < 8; ni++)
#pragma unroll
            for (int r = 0; r < 4; r++) acc[mi][ni][r] = 0.f;

#define GEMM_LOAD(st, k0)                                                     \
    {                                                                          \
        uint32_t s0 = sbase + (st) * (4 * TILE_W) * 4;                         \
        _Pragma("unroll")                                                      \
        for (int j = 0; j < 8; j++) {                                          \
            int idx = tid + j * 256;                                           \
            int arr = j >> 1;                                                  \
            int r = (idx >> 2) & 127, c = idx & 3;                             \
            cp_async16_sa(s0 + (arr * TILE_W + r * PW + c * 4) * 4,            \
                          gptr[arr] + (size_t)r * K + (k0) + c * 8);           \
        }                                                                      \
        cp_commit();                                                           \
    }

    const int NIT = K / 32;
    GEMM_LOAD(0, 0);

    for (int it = 0; it < NIT; ++it) {
        const int st = it & 1;
        // Single barrier per iteration: after it, all warps have finished
        // MMA(it-1) (program order) and everyone's loads for buf(st) landed.
        asm volatile("cp.async.wait_group 0;\n" ::: "memory");
        __syncthreads();
        // Safe to overwrite buf(st^1) now (read by MMA(it-1), done by barrier).
        if (it + 1 < NIT) GEMM_LOAD(st ^ 1, (it + 1) * 32);

        const uint32_t sA_h = sbase + (st * 4 * TILE_W) * 4;
        const uint32_t sA_l = sA_h + TILE_W * 4;
        const uint32_t sB_h = sA_h + 2 * TILE_W * 4;
        const uint32_t sB_l = sA_h + 3 * TILE_W * 4;

#pragma unroll
        for (int ch = 0; ch < 2; ch++) {
            const uint32_t kb = (uint32_t)(ch * 8 * 4);
            uint32_t ah[2][4], al[2][4];
#pragma unroll
            for (int mi = 0; mi < 2; mi++) {
                ldsm_x4(sA_h + a_off + (uint32_t)(mi * 16 * PW * 4) + kb, ah[mi]);
                ldsm_x4(sA_l + a_off + (uint32_t)(mi * 16 * PW * 4) + kb, al[mi]);
            }
#pragma unroll
            for (int p = 0; p < 4; p++) {
                uint32_t bh[4], bl[4];
                ldsm_x4(sB_h + b_off + (uint32_t)(p * 16 * PW * 4) + kb, bh);
                ldsm_x4(sB_l + b_off + (uint32_t)(p * 16 * PW * 4) + kb, bl);
#pragma unroll
                for (int s = 0; s < 2; s++) {
                    const int ni = 2 * p + s;
#pragma unroll
                    for (int mi = 0; mi < 2; mi++) {
                        mma_bf16(acc[mi][ni], ah[mi], bh[2 * s], bh[2 * s + 1]);
                        mma_bf16(acc[mi][ni], al[mi], bh[2 * s], bh[2 * s + 1]);
                        mma_bf16(acc[mi][ni], ah[mi], bl[2 * s], bl[2 * s + 1]);
                    }
                }
            }
        }
        // no trailing barrier
    }

#pragma unroll
    for (int mi = 0; mi < 2; mi++) {
        const int row = blockIdx.y * 128 + wm + mi * 16 + g;
#pragma unroll
        for (int ni = 0; ni < 8; ni++) {
            const int col = blockIdx.x * 128 + wn + ni * 8 + 2 * tg;
            *reinterpret_cast<float2*>(C + (size_t)row * N + col) =
                make_float2(acc[mi][ni][0], acc[mi][ni][1]);
            *reinterpret_cast<float2*>(C + (size_t)(row + 8) * N + col) =
                make_float2(acc[mi][ni][2], acc[mi][ni][3]);
        }
    }
}

// ---------------------------------------------------------------------------
// RoPE + scatter (unchanged)
// ---------------------------------------------------------------------------
__global__ void rope_scatter_kernel(const int* __restrict__ positions) {
    const int total = B_ * S_ * (NH_ + NKV_) * (D_ / 2);
    int idx = blockIdx.x * blockDim.x + threadIdx.x;
    if (idx >= total) return;

    const int d = idx & 31;
    int t = idx >> 5;
    const int h = t % (NH_ + NKV_); t /= (NH_ + NKV_);
    const int s = t % S_;
    const int b = t / S_;

    const float pos = (float)positions[s];
    const float inv = powf(10000.0f, -(float)(2 * d) / (float)D_);
    const float freq = pos * inv;
    const double dr = (double)freq;
    const double kq = floor(dr * 0.15915494309189534 + 0.5);
    const float  rr = (float)(dr - kq * 6.283185307179586477);
    float sn, cs;
    sincosf(rr, &sn, &cs);

    const float* base = g_qkv + (size_t)(b * S_ + s) * QKVF;
    float x0, x1, scale;
    bf16 *dhi, *dlo;
    if (h < NH_) {
        x0 = base[h * D_ + d];
        x1 = base[h * D_ + d + 32];
        size_t off = (((size_t)(b * NH_ + h)) * S_ + s) * D_;
        dhi = g_q_hi + off; dlo = g_q_lo + off;
        scale = 0.125f;
    } else {
        const int hk = h - NH_;
        x0 = base[NH_ * D_ + hk * D_ + d];
        x1 = base[NH_ * D_ + hk * D_ + d + 32];
        size_t off = (((size_t)(b * NKV_ + hk)) * S_ + s) * D_;
        dhi = g_k_hi + off; dlo = g_k_lo + off;
        scale = 1.0f;
    }
    float v0 = (x0 * cs - x1 * sn) * scale;
    float v1 = (x1 * cs + x0 * sn) * scale;
    bf16 h0 = __float2bfloat16(v0);
    bf16 h1 = __float2bfloat16(v1);
    dhi[d]      = h0;
    dhi[d + 32] = h1;
    dlo[d]      = __float2bfloat16(v0 - __bfloat162float(h0));
    dlo[d + 32] = __float2bfloat16(v1 - __bfloat162float(h1));
}

__global__ void vtranspose_kernel() {
    __shared__ float t[32][65];
    const int s0 = blockIdx.x * 32;
    const int kh = blockIdx.y;
    const int b  = blockIdx.z;
    const int tid = threadIdx.x;

    const float* src = g_qkv + (size_t)b * S_ * QKVF + (NH_ + NKV_) * D_ + kh * D_;
#pragma unroll
    for (int j = 0; j < 8; j++) {
        int e = tid + j * 256;
        int s = e >> 6, d = e & 63;
        t[s][d] = src[(size_t)(s0 + s) * QKVF + d];
    }
    __syncthreads();

    bf16* dhi = g_vt_hi + ((size_t)(b * NKV_ + kh)) * D_ * S_;
    bf16* dlo = g_vt_lo + ((size_t)(b * NKV_ + kh)) * D_ * S_;
#pragma unroll
    for (int j = 0; j < 8; j++) {
        int e = tid + j * 256;
        int d = e >> 5, s = e & 31;
        float x = t[s][d];
        bf16 h = __float2bfloat16(x);
        dhi[(size_t)d * S_ + s0 + s] = h;
        dlo[(size_t)d * S_ + s0 + s] = __float2bfloat16(x - __bfloat162float(h));
    }
}

// ---------------------------------------------------------------------------
// bf16x3 causal flash attention, ldmatrix loads, ONE barrier per k-tile.
// ---------------------------------------------------------------------------
#define AW 36
#define AT_W (64 * AW)
#define ATTN_SMEM (12 * AT_W * 4)

__global__ __launch_bounds__(128, 2)
void attn_kernel(float* /*unused*/) {
    extern __shared__ uint32_t sw[];
    const uint32_t sbase = smem_u32(sw);

    const int qtile = gridDim.x - 1 - blockIdx.x;
    const int h = blockIdx.y;
    const int b = blockIdx.z;
    const int kvh = h / GQA_;
    const int q0 = qtile * 64;

    const bf16* qh_g = g_q_hi + (((size_t)(b * NH_ + h)) * S_ + q0) * D_;
    const bf16* ql_g = g_q_lo + (((size_t)(b * NH_ + h)) * S_ + q0) * D_;
    const bf16* kh_g = g_k_hi + ((size_t)(b * NKV_ + kvh)) * S_ * D_;
    const bf16* kl_g = g_k_lo + ((size_t)(b * NKV_ + kvh)) * S_ * D_;
    const bf16* vh_g = g_vt_hi + ((size_t)(b * NKV_ + kvh)) * D_ * S_;
    const bf16* vl_g = g_vt_lo + ((size_t)(b * NKV_ + kvh)) * D_ * S_;

    const int tid  = threadIdx.x;
    const int wid  = tid >> 5;
    const int lane = tid & 31;
    const int g  = lane >> 2;
    const int tg = lane & 3;
    const int wm = wid * 16;

    const uint32_t aq_off = (uint32_t)(((wm + (lane & 15)) * AW + (lane >> 4) * 4) * 4);
    const uint32_t bk_off = (uint32_t)(((((lane >> 4) << 3) + (lane & 7)) * AW
                                        + ((lane >> 3) & 1) * 4) * 4);

#pragma unroll
    for (int j = 0; j < 8; j++) {
        int idx = tid + j * 128;
        int r = (idx >> 3) & 63, c = idx & 7;
        const bf16* src = (j >> 2) ? ql_g : qh_g;
        cp_async16_sa(sbase + ((j >> 2) * AT_W + r * AW + c * 4) * 4,
                      src + (size_t)r * D_ + c * 8);
    }
    cp_commit();

#define ATTN_LOAD_KV(st, kt)                                                    \
    {                                                                            \
        _Pragma("unroll")                                                        \
        for (int j = 0; j < 16; j++) {                                           \
            int idx = tid + j * 128;                                              \
            int arr = j >> 2;                                                     \
            int r = (idx >> 3) & 63, c = idx & 7;                                 \
            int tile = (arr < 2 ? 4 : 8) + 2 * (st) + (arr & 1);                  \
            const bf16* src;                                                      \
            size_t goff;                                                          \
            if (arr == 0)      { src = kh_g; goff = (size_t)((kt) * 64 + r) * D_ + c * 8; } \
            else if (arr == 1) { src = kl_g; goff = (size_t)((kt) * 64 + r) * D_ + c * 8; } \
            else if (arr == 2) { src = vh_g; goff = (size_t)r * S_ + (kt) * 64 + c * 8; }   \
            else               { src = vl_g; goff = (size_t)r * S_ + (kt) * 64 + c * 8; }   \
            cp_async16_sa(sbase + (tile * AT_W + r * AW + c * 4) * 4, src + goff); \
        }                                                                         \
        cp_commit();                                                              \
    }

    ATTN_LOAD_KV(0, 0);

    float oacc[8][4];
    float m0 = -1e30f, m1 = -1e30f, l0 = 0.f, l1 = 0.f;
#pragma unroll
    for (int ni = 0; ni < 8; ni++)
#pragma unroll
        for (int r = 0; r < 4; r++) oacc[ni][r] = 0.f;

    const int gq0 = q0 + wm + g;
    const int gq1 = gq0 + 8;

    const uint32_t Qh_b = sbase;
    const uint32_t Ql_b = sbase + AT_W * 4;
    uint32_t* Ph = sw + 2 * AT_W;
    uint32_t* Pl = sw + 3 * AT_W;
    const uint32_t Ph_b = sbase + 2 * AT_W * 4;
    const uint32_t Pl_b = sbase + 3 * AT_W * 4;

    for (int kt = 0; kt <= qtile; kt++) {
        const int cur = kt & 1;
        // Single barrier per k-tile: all warps finished the previous tile's
        // MMAs (program order) and everyone's loads for buffer cur landed.
        asm volatile("cp.async.wait_group 0;\n" ::: "memory");
        __syncthreads();
        if (kt + 1 <= qtile) ATTN_LOAD_KV(cur ^ 1, kt + 1);

        const uint32_t Kh_b = sbase + (4 + 2 * cur) * AT_W * 4;
        const uint32_t Kl_b = sbase + (5 + 2 * cur) * AT_W * 4;
        const uint32_t Vh_b = sbase + (8 + 2 * cur) * AT_W * 4;
        const uint32_t Vl_b = sbase + (9 + 2 * cur) * AT_W * 4;

        float sacc[8][4];
#pragma unroll
        for (int ni = 0; ni < 8; ni++)
#pragma unroll
            for (int r = 0; r < 4; r++) sacc[ni][r] = 0.f;

#pragma unroll
        for (int ch = 0; ch < 4; ch++) {
            const uint32_t kb = (uint32_t)(ch * 8 * 4);
            uint32_t qh[4], ql[4];
            ldsm_x4(Qh_b + aq_off + kb, qh);
            ldsm_x4(Ql_b + aq_off + kb, ql);
#pragma unroll
            for (int p = 0; p < 4; p++) {
                uint32_t kh4[4], kl4[4];
                ldsm_x4(Kh_b + bk_off + (uint32_t)(p * 16 * AW * 4) + kb, kh4);
                ldsm_x4(Kl_b + bk_off + (uint32_t)(p * 16 * AW * 4) + kb, kl4);
#pragma unroll
                for (int s = 0; s < 2; s++) {
                    const int ni = 2 * p + s;
                    mma_bf16(sacc[ni], qh, kh4[2 * s], kh4[2 * s + 1]);
                    mma_bf16(sacc[ni], ql, kh4[2 * s], kh4[2 * s + 1]);
                    mma_bf16(sacc[ni], qh, kl4[2 * s], kl4[2 * s + 1]);
                }
            }
        }

        if (kt == qtile) {
#pragma unroll
            for (int ni = 0; ni < 8; ni++) {
                const int col = kt * 64 + ni * 8 + 2 * tg;
                if (col     > gq0) sacc[ni][0] = -1e30f;
                if (col + 1 > gq0) sacc[ni][1] = -1e30f;
                if (col     > gq1) sacc[ni][2] = -1e30f;
                if (col + 1 > gq1) sacc[ni][3] = -1e30f;
            }
        }

        float mx0 = -1e30f, mx1 = -1e30f;
#pragma unroll
        for (int ni = 0; ni < 8; ni++) {
            mx0 = fmaxf(mx0, fmaxf(sacc[ni][0], sacc[ni][1]));
            mx1 = fmaxf(mx1, fmaxf(sacc[ni][2], sacc[ni][3]));
        }
        mx0 = fmaxf(mx0, __shfl_xor_sync(0xffffffffu, mx0, 1));
        mx0 = fmaxf(mx0, __shfl_xor_sync(0xffffffffu, mx0, 2));
        mx1 = fmaxf(mx1, __shfl_xor_sync(0xffffffffu, mx1, 1));
        mx1 = fmaxf(mx1, __shfl_xor_sync(0xffffffffu, mx1, 2));

        const float mn0 = fmaxf(m0, mx0);
        const float mn1 = fmaxf(m1, mx1);
        const float corr0 = __expf(m0 - mn0);
        const float corr1 = __expf(m1 - mn1);
        float rs0 = 0.f, rs1 = 0.f;
#pragma unroll
        for (int ni = 0; ni < 8; ni++) {
            float p0 = __expf(sacc[ni][0] - mn0);
            float p1 = __expf(sacc[ni][1] - mn0);
            float p2 = __expf(sacc[ni][2] - mn1);
            float p3 = __expf(sacc[ni][3] - mn1);
            sacc[ni][0] = p0; sacc[ni][1] = p1;
            sacc[ni][2] = p2; sacc[ni][3] = p3;
            rs0 += p0 + p1;
            rs1 += p2 + p3;
        }
        rs0 += __shfl_xor_sync(0xffffffffu, rs0, 1);
        rs0 += __shfl_xor_sync(0xffffffffu, rs0, 2);
        rs1 += __shfl_xor_sync(0xffffffffu, rs1, 1);
        rs1 += __shfl_xor_sync(0xffffffffu, rs1, 2);
        l0 = l0 * corr0 + rs0;
        l1 = l1 * corr1 + rs1;
        m0 = mn0;
        m1 = mn1;
#pragma unroll
        for (int ni = 0; ni < 8; ni++) {
            oacc[ni][0] *= corr0;
            oacc[ni][1] *= corr0;
            oacc[ni][2] *= corr1;
            oacc[ni][3] *= corr1;
        }

        // P -> smem (split bf16; rows are warp-local, so __syncwarp suffices)
#pragma unroll
        for (int ni = 0; ni < 8; ni++) {
            const int cw = ni * 4 + tg;
            uint32_t h0, L0, h1, L1;
            split2(sacc[ni][0], sacc[ni][1], h0, L0);
            split2(sacc[ni][2], sacc[ni][3], h1, L1);
            Ph[(wm + g) * AW + cw] = h0;
            Pl[(wm + g) * AW + cw] = L0;
            Ph[(wm + g + 8) * AW + cw] = h1;
            Pl[(wm + g + 8) * AW + cw] = L1;
        }
        __syncwarp();

#pragma unroll
        for (int ch = 0; ch < 4; ch++) {
            const uint32_t kb = (uint32_t)(ch * 8 * 4);
            uint32_t ph[4], pl[4];
            ldsm_x4(Ph_b + aq_off + kb, ph);
            ldsm_x4(Pl_b + aq_off + kb, pl);
#pragma unroll
            for (int p = 0; p < 4; p++) {
                uint32_t vh4[4], vl4[4];
                ldsm_x4(Vh_b + bk_off + (uint32_t)(p * 16 * AW * 4) + kb, vh4);
                ldsm_x4(Vl_b + bk_off + (uint32_t)(p * 16 * AW * 4) + kb, vl4);
#pragma unroll
                for (int s = 0; s < 2; s++) {
                    const int ni = 2 * p + s;
                    mma_bf16(oacc[ni], ph, vh4[2 * s], vh4[2 * s + 1]);
                    mma_bf16(oacc[ni], pl, vh4[2 * s], vh4[2 * s + 1]);
                    mma_bf16(oacc[ni], ph, vl4[2 * s], vl4[2 * s + 1]);
                }
            }
        }
        // no trailing barrier
    }

    const float il0 = 1.0f / l0;
    const float il1 = 1.0f / l1;
    uint32_t* ch_w = reinterpret_cast<uint32_t*>(g_ctx_hi);
    uint32_t* cl_w = reinterpret_cast<uint32_t*>(g_ctx_lo);
    const size_t off0 = (((size_t)(b * S_ + gq0)) * (NH_ * D_) + h * D_) >> 1;
    const size_t off1 = (((size_t)(b * S_ + gq1)) * (NH_ * D_) + h * D_) >> 1;
#pragma unroll
    for (int ni = 0; ni < 8; ni++) {
        const int cw = ni * 4 + tg;
        uint32_t h0, L0, h1, L1;
        split2(oacc[ni][0] * il0, oacc[ni][1] * il0, h0, L0);
        split2(oacc[ni][2] * il1, oacc[ni][3] * il1, h1, L1);
        ch_w[off0 + cw] = h0;
        cl_w[off0 + cw] = L0;
        ch_w[off1 + cw] = h1;
        cl_w[off1 + cw] = L1;
    }
}

// ---------------------------------------------------------------------------
// Launch
// ---------------------------------------------------------------------------
extern "C" void kernel_launch(void* const* d_in, const int* in_sizes, int n_in,
                              void* d_out, int out_size) {
    const int*   positions = (const int*)d_in[0];
    const float* hidden    = (const float*)d_in[1];
    const float* Wqkv      = (const float*)d_in[2];
    const float* Wo        = (const float*)d_in[3];
    float* out = (float*)d_out;

    float* qkv_p;
    bf16 *hh, *hl, *wqh, *wql, *woh, *wol, *cth, *ctl;
    cudaGetSymbolAddress((void**)&qkv_p, g_qkv);
    cudaGetSymbolAddress((void**)&hh,  g_hid_hi);
    cudaGetSymbolAddress((void**)&hl,  g_hid_lo);
    cudaGetSymbolAddress((void**)&wqh, g_wqkv_hi);
    cudaGetSymbolAddress((void**)&wql, g_wqkv_lo);
    cudaGetSymbolAddress((void**)&woh, g_wo_hi);
    cudaGetSymbolAddress((void**)&wol, g_wo_lo);
    cudaGetSymbolAddress((void**)&cth, g_ctx_hi);
    cudaGetSymbolAddress((void**)&ctl, g_ctx_lo);

    cudaFuncSetAttribute(gemm_bf16x3, cudaFuncAttributeMaxDynamicSharedMemorySize, GSMEM);
    cudaFuncSetAttribute(gemm_bf16x3, cudaFuncAttributePreferredSharedMemoryCarveout, 100);
    cudaFuncSetAttribute(attn_kernel, cudaFuncAttributeMaxDynamicSharedMemorySize, ATTN_SMEM);
    cudaFuncSetAttribute(attn_kernel, cudaFuncAttributePreferredSharedMemoryCarveout, 100);

    // 0. Pre-split operands
    {
        int n4 = B_ * S_ * H_ / 4;
        split_kernel<<<(n4 + 255) / 256, 256>>>(hidden, (uint2*)hh, (uint2*)hl, n4);
        split_transpose_kernel<<<dim3(QKVF / 32, H_ / 32), dim3(32, 8)>>>(Wqkv, wqh, wql, H_, QKVF);
        split_transpose_kernel<<<dim3(H_ / 32, H_ / 32), dim3(32, 8)>>>(Wo, woh, wol, H_, H_);
    }

    // 1. QKV projection
    gemm_bf16x3<<<dim3(QKVF / 128, (B_ * S_) / 128), 256, GSMEM>>>(
        hh, hl, wqh, wql, qkv_p, B_ * S_, QKVF, H_);

    // 2. RoPE + scatter (split) + V split-transpose
    {
        const int total = B_ * S_ * (NH_ + NKV_) * (D_ / 2);
        rope_scatter_kernel<<<(total + 255) / 256, 256>>>(positions);
        vtranspose_kernel<<<dim3(S_ / 32, NKV_, B_), 256>>>();
    }

    // 3. Causal GQA flash attention
    attn_kernel<<<dim3(S_ / 64, NH_, B_), 128, ATTN_SMEM>>>(nullptr);

    // 4. Output projection
    gemm_bf16x3<<<dim3(H_ / 128, (B_ * S_) / 128), 256, GSMEM>>>(
        cth, ctl, woh, wol, out, B_ * S_, H_, NH_ * D_);
}